// round 11
// baseline (speedup 1.0000x reference)
#include <cuda_runtime.h>
#include <cuda_fp16.h>
#include <math.h>
#include <stdint.h>

// Problem constants
#define Bq   2
#define Lq   2048
#define Hq   1024
#define Eq   2048
#define Nq   16
#define Rq   64
#define TOK  (Bq*Lq)        // 4096 tokens
#define PC   96             // packed proj cols: 64 (delta) + 16 (B) + 16 (C)
#define PCP  128            // padded N for P-GEMM
#define KSPLIT 8
#define NCHUNK 32           // scan chunks
#define CT    (Lq/NCHUNK)   // 64 timesteps per chunk
#define NCHAN (Bq*Eq)       // 4096 channels

// ---------------- device scratch (allocation-free) ----------------
__device__ __align__(16) __half g_xn[TOK*Hq];      // layernormed input (fp16)
__device__ __align__(16) __half g_u[TOK*Eq];       // silu(u) fp16
__device__ __align__(16) __half g_gate[TOK*Eq];    // silu(gate) fp16
__device__ __align__(16) __half g_y[TOK*Eq];       // scan output fp16
__device__ __align__(16) float  g_P[TOK*PC];       // [delta_proj(64) | B(16) | C(16)] f32
__device__ __align__(16) __half g_Ph[TOK*64];      // delta-proj part, fp16 (GEMM input)
__device__ __align__(16) float  g_Ppart[KSPLIT*TOK*PC];
__device__ __align__(16) float  g_delta[TOK*Eq];   // softplus delta f32
__device__ __align__(16) __half g_WcatT[PCP*Eq];   // [delta|B|C]^T padded, fp16
__device__ float g_bcat[PC];
__device__ __align__(16) __half g_WtIn[2*Eq*Hq];   // W_in^T  [4096][1024] fp16
__device__ __align__(16) __half g_WtDt[Eq*Rq];     // W_dt^T  [2048][64]   fp16
__device__ __align__(16) __half g_WtOut[Hq*Eq];    // W_out^T [1024][2048] fp16
// chunked-scan state: [chunk][chan][n]
__device__ __align__(16) float g_ap [NCHUNK*NCHAN*Nq];
__device__ __align__(16) float g_c  [NCHUNK*NCHAN*Nq];
__device__ __align__(16) float g_hin[NCHUNK*NCHAN*Nq];

__device__ __forceinline__ uint32_t sptr(const void* p) {
    return (uint32_t)__cvta_generic_to_shared(p);
}

// ---------------- LayerNorm (writes fp16 xn) ----------------
__global__ void ln_kernel(const float* __restrict__ x,
                          const float* __restrict__ gamma,
                          const float* __restrict__ beta) {
    int m = blockIdx.x;
    const float* row = x + (size_t)m*Hq;
    float s = 0.f, s2 = 0.f;
    for (int i = threadIdx.x; i < Hq; i += blockDim.x) {
        float v = row[i]; s += v; s2 += v*v;
    }
    __shared__ float sh[64];
    for (int o = 16; o; o >>= 1) {
        s  += __shfl_xor_sync(~0u, s,  o);
        s2 += __shfl_xor_sync(~0u, s2, o);
    }
    int wid = threadIdx.x >> 5, lane = threadIdx.x & 31;
    if (lane == 0) { sh[wid] = s; sh[32+wid] = s2; }
    __syncthreads();
    if (wid == 0) {
        int nw = blockDim.x >> 5;
        s  = (lane < nw) ? sh[lane]    : 0.f;
        s2 = (lane < nw) ? sh[32+lane] : 0.f;
        for (int o = 16; o; o >>= 1) {
            s  += __shfl_xor_sync(~0u, s,  o);
            s2 += __shfl_xor_sync(~0u, s2, o);
        }
        if (lane == 0) { sh[0] = s; sh[1] = s2; }
    }
    __syncthreads();
    float mu  = sh[0] * (1.f/Hq);
    float var = sh[1] * (1.f/Hq) - mu*mu;
    float inv = rsqrtf(var + 1e-5f);
    for (int i = threadIdx.x; i < Hq; i += blockDim.x) {
        g_xn[(size_t)m*Hq + i] = __float2half_rn((row[i]-mu)*inv*gamma[i] + beta[i]);
    }
}

// ---------------- tiled transpose to fp16: dst[c][r] = h(src[r][c]) ----------
__global__ void transpose_h(const float* __restrict__ src, __half* __restrict__ dst,
                            int R, int Cc) {
    __shared__ float t[32][33];
    int c0 = blockIdx.x*32, r0 = blockIdx.y*32;
    for (int i = threadIdx.y; i < 32; i += 8)
        t[i][threadIdx.x] = src[(size_t)(r0+i)*Cc + c0 + threadIdx.x];
    __syncthreads();
    for (int i = threadIdx.y; i < 32; i += 8)
        dst[(size_t)(c0+i)*R + r0 + threadIdx.x] = __float2half_rn(t[threadIdx.x][i]);
}

// ---------------- pack W_delta|W_B|W_C transposed+padded, fp16 --------------
__global__ void pack_kernel(const float* __restrict__ Wd, const float* __restrict__ Wb,
                            const float* __restrict__ Wc, const float* __restrict__ bd,
                            const float* __restrict__ bb, const float* __restrict__ bc) {
    int i = blockIdx.x*blockDim.x + threadIdx.x;
    if (i < PCP*Eq) {
        int c = i / Eq, k = i % Eq;
        float v = 0.f;
        if (c < 64)      v = Wd[k*64 + c];
        else if (c < 80) v = Wb[k*16 + (c-64)];
        else if (c < 96) v = Wc[k*16 + (c-80)];
        g_WcatT[i] = __float2half_rn(v);
    }
    if (i < PC) {
        g_bcat[i] = (i < 64) ? bd[i] : ((i < 80) ? bb[i-64] : bc[i-80]);
    }
}

// ---------------- split-K reduction for P (f32 + fp16 delta part) -----------
__global__ void reduceP_kernel() {
    int i = blockIdx.x*blockDim.x + threadIdx.x;
    if (i >= TOK*PC) return;
    int c = i % PC, m = i / PC;
    float s = g_bcat[c];
    #pragma unroll
    for (int z = 0; z < KSPLIT; z++) s += g_Ppart[(size_t)z*TOK*PC + i];
    g_P[i] = s;
    if (c < 64) g_Ph[(size_t)m*64 + c] = __float2half_rn(s);
}

// ======== fp16 m16n8k16 GEMM, 8 warps, 64x32 warptiles, ldmatrix ============
enum { EPI_SPLIT_SILU = 1, EPI_SOFTPLUS = 2, EPI_RES = 3, EPI_PART = 4 };

#define MMA_F16(c0,c1,c2,c3,a0,a1,a2,a3,b0,b1) \
    asm volatile("mma.sync.aligned.m16n8k16.row.col.f32.f16.f16.f32 " \
                 "{%0,%1,%2,%3},{%4,%5,%6,%7},{%8,%9},{%0,%1,%2,%3};" \
                 : "+f"(c0),"+f"(c1),"+f"(c2),"+f"(c3) \
                 : "r"(a0),"r"(a1),"r"(a2),"r"(a3),"r"(b0),"r"(b1))

#define LDSM_X4(r0,r1,r2,r3,addr) \
    asm volatile("ldmatrix.sync.aligned.m8n8.x4.shared.b16 {%0,%1,%2,%3}, [%4];" \
                 : "=r"(r0),"=r"(r1),"=r"(r2),"=r"(r3) : "r"(addr))

template<int N> __device__ __forceinline__ void cp_wait() {
    asm volatile("cp.async.wait_group %0;" :: "n"(N));
}
__device__ __forceinline__ void cp_commit() {
    asm volatile("cp.async.commit_group;" ::);
}

#define HBM 128
#define HBN 128
#define HBK 32
#define HSTAGE 4
#define HLD 40                      // halves per row (32 + 8 pad) = 80 bytes
#define HSTG (HBM*HLD)              // halves per stage tile (5120)
#define H_SMEM (HSTAGE*HSTG*2*2)    // A + B regions, bytes (81920)

template<int EPI>
__global__ void __launch_bounds__(256, 2)
gemm_h(const __half* __restrict__ A, int lda,
       const __half* __restrict__ Bt, int ldb,    // [N][K] K-major
       const float* __restrict__ bias,
       void* __restrict__ Cv, int ldc,
       const float* __restrict__ resid,           // residual (RES)
       __half* __restrict__ gate,                 // gate out (SPLIT_SILU)
       int M, int N, int K, int Kchunk)
{
    extern __shared__ __half smh[];
    __half* Asm = smh;
    __half* Bsm = smh + HSTAGE*HSTG;
    const uint32_t aBase = sptr(Asm);
    const uint32_t bBase = sptr(Bsm);

    const int tid  = threadIdx.x;
    const int lane = tid & 31;
    const int warp = tid >> 5;
    const int wr   = warp & 1;          // 2 x 64 rows
    const int wc   = warp >> 1;         // 4 x 32 cols
    const int m0   = blockIdx.y * HBM;
    const int n0   = blockIdx.x * HBN;
    const int Koff = blockIdx.z * Kchunk;

    // ldmatrix per-lane base offsets (halves; *2 for bytes at use site)
    const uint32_t aRow = wr*64 + (lane & 15);
    const uint32_t aCol = (lane >> 4) * 8;
    // B non-trans: lanes 0-7 rows n0..7 @k0 | 8-15 @k0+8 | 16-23 rows n8..15 @k0 | 24-31 @k0+8
    const uint32_t bRow = wc*32 + (lane & 7) + ((lane >> 4) << 3);
    const uint32_t bCol = ((lane >> 3) & 1) * 8;

    auto issue = [&](int it, int buf) {
        int k0 = Koff + it * HBK;
        #pragma unroll
        for (int j = 0; j < 2; j++) {
            int id = tid + j*256;
            int row = id >> 2, slot = id & 3;
            const __half* as = A  + (size_t)(m0 + row)*lda + k0 + slot*8;
            const __half* bs = Bt + (size_t)(n0 + row)*ldb + k0 + slot*8;
            asm volatile("cp.async.ca.shared.global [%0], [%1], 16;\n"
                         :: "r"(aBase + buf*(HSTG*2) + row*80 + slot*16), "l"(as));
            asm volatile("cp.async.ca.shared.global [%0], [%1], 16;\n"
                         :: "r"(bBase + buf*(HSTG*2) + row*80 + slot*16), "l"(bs));
        }
    };

    float acc[4][4][4];
    #pragma unroll
    for (int i = 0; i < 4; i++)
        #pragma unroll
        for (int j = 0; j < 4; j++)
            #pragma unroll
            for (int k = 0; k < 4; k++) acc[i][j][k] = 0.f;

    const int nIter = Kchunk / HBK;
    #pragma unroll
    for (int s = 0; s < HSTAGE-1; s++) {
        if (s < nIter) issue(s, s);
        cp_commit();
    }

    for (int it = 0; it < nIter; it++) {
        cp_wait<HSTAGE-2>();
        __syncthreads();
        int nx = it + HSTAGE - 1;
        if (nx < nIter) issue(nx, nx & (HSTAGE-1));
        cp_commit();

        int buf = it & (HSTAGE-1);
        uint32_t aB = aBase + buf*(HSTG*2);
        uint32_t bB = bBase + buf*(HSTG*2);

        #pragma unroll
        for (int kk = 0; kk < 2; kk++) {
            uint32_t af[4][4], bf[4][2];
            #pragma unroll
            for (int mt = 0; mt < 4; mt++) {
                uint32_t ad = aB + ((aRow + mt*16)*HLD + kk*16 + aCol)*2;
                LDSM_X4(af[mt][0], af[mt][1], af[mt][2], af[mt][3], ad);
            }
            #pragma unroll
            for (int ntp = 0; ntp < 2; ntp++) {
                uint32_t bd = bB + ((bRow + ntp*16)*HLD + kk*16 + bCol)*2;
                LDSM_X4(bf[2*ntp][0], bf[2*ntp][1], bf[2*ntp+1][0], bf[2*ntp+1][1], bd);
            }
            #pragma unroll
            for (int mt = 0; mt < 4; mt++)
                #pragma unroll
                for (int nt = 0; nt < 4; nt++)
                    MMA_F16(acc[mt][nt][0], acc[mt][nt][1], acc[mt][nt][2], acc[mt][nt][3],
                            af[mt][0], af[mt][1], af[mt][2], af[mt][3],
                            bf[nt][0], bf[nt][1]);
        }
    }

    // epilogue: pair (q0,q1)/(q2,q3) -> column-adjacent vector stores
    #pragma unroll
    for (int mt = 0; mt < 4; mt++) {
        #pragma unroll
        for (int nt = 0; nt < 4; nt++) {
            #pragma unroll
            for (int half = 0; half < 2; half++) {
                int gm = m0 + wr*64 + mt*16 + (lane >> 2) + half*8;
                int gn = n0 + wc*32 + nt*8 + 2*(lane & 3);
                float v0 = acc[mt][nt][half*2 + 0];
                float v1 = acc[mt][nt][half*2 + 1];
                if (EPI == EPI_PART) {
                    if (gn < N) {
                        float* dst = (float*)Cv + (size_t)blockIdx.z*TOK*PC + (size_t)gm*ldc + gn;
                        dst[0] = v0;
                        if (gn + 1 < N) dst[1] = v1;
                    }
                    continue;
                }
                v0 += bias[gn]; v1 += bias[gn+1];
                if (EPI == EPI_SPLIT_SILU) {
                    float s0 = v0 / (1.f + __expf(-v0));
                    float s1 = v1 / (1.f + __expf(-v1));
                    __half2 hv = __floats2half2_rn(s0, s1);
                    if (gn < Eq) *(__half2*)((__half*)Cv + (size_t)gm*Eq + gn) = hv;
                    else         *(__half2*)(gate + (size_t)gm*Eq + gn - Eq)  = hv;
                } else if (EPI == EPI_SOFTPLUS) {
                    float2 f2;
                    f2.x = (v0 > 20.f) ? v0 : log1pf(__expf(v0));
                    f2.y = (v1 > 20.f) ? v1 : log1pf(__expf(v1));
                    *(float2*)((float*)Cv + (size_t)gm*ldc + gn) = f2;
                } else { // EPI_RES
                    const float2 r2 = *(const float2*)(resid + (size_t)gm*ldc + gn);
                    float2 f2; f2.x = v0 + r2.x; f2.y = v1 + r2.y;
                    *(float2*)((float*)Cv + (size_t)gm*ldc + gn) = f2;
                }
            }
        }
    }
}

// ---------------- chunked selective scan ----------------
#define LOG2E 1.4426950408889634f

__global__ void __launch_bounds__(256)
scan_p1(const float* __restrict__ A_log) {
    int gw    = blockIdx.x*8 + (threadIdx.x >> 5);
    int lane  = threadIdx.x & 31;
    int egrp  = gw & 127;
    int chunk = gw >> 7;
    int c = egrp*32 + lane;
    int b = c >> 11;
    int e = c & (Eq-1);
    int t0 = chunk * CT;

    float Aen[Nq];
    #pragma unroll
    for (int n = 0; n < Nq; n++)
        Aen[n] = -__expf(A_log[e*Nq + n]) * LOG2E;

    float h[Nq], ap[Nq];
    #pragma unroll
    for (int n = 0; n < Nq; n++) { h[n] = 0.f; ap[n] = 1.f; }

    const float*  dp = g_delta + ((size_t)b*Lq + t0)*Eq + e;
    const __half* up = g_u     + ((size_t)b*Lq + t0)*Eq + e;

    #pragma unroll 2
    for (int t = 0; t < CT; t++) {
        float d  = dp[(size_t)t*Eq];
        float xv = __half2float(up[(size_t)t*Eq]);
        float dx = d * xv;
        const float4* pB4 = (const float4*)(g_P + ((size_t)b*Lq + t0 + t)*PC + 64);
        #pragma unroll
        for (int q = 0; q < 4; q++) {
            float4 Bv = __ldg(pB4 + q);
            float bb[4] = {Bv.x, Bv.y, Bv.z, Bv.w};
            #pragma unroll
            for (int r = 0; r < 4; r++) {
                int n = q*4 + r;
                float da = exp2f(d * Aen[n]);
                ap[n] *= da;
                h[n] = fmaf(da, h[n], dx * bb[r]);
            }
        }
    }
    float4* apo = (float4*)(g_ap + ((size_t)chunk*NCHAN + c)*Nq);
    float4* co  = (float4*)(g_c  + ((size_t)chunk*NCHAN + c)*Nq);
    #pragma unroll
    for (int q = 0; q < 4; q++) {
        apo[q] = make_float4(ap[q*4], ap[q*4+1], ap[q*4+2], ap[q*4+3]);
        co[q]  = make_float4(h[q*4],  h[q*4+1],  h[q*4+2],  h[q*4+3]);
    }
}

__global__ void __launch_bounds__(256)
scan_p2() {
    int i = blockIdx.x*blockDim.x + threadIdx.x;
    if (i >= NCHAN*Nq) return;
    float hin = 0.f;
    #pragma unroll
    for (int k = 0; k < NCHUNK; k++) {
        size_t idx = (size_t)k*NCHAN*Nq + i;
        g_hin[idx] = hin;
        hin = g_ap[idx]*hin + g_c[idx];
    }
}

__global__ void __launch_bounds__(256)
scan_p3(const float* __restrict__ A_log, const float* __restrict__ Dv) {
    int gw    = blockIdx.x*8 + (threadIdx.x >> 5);
    int lane  = threadIdx.x & 31;
    int egrp  = gw & 127;
    int chunk = gw >> 7;
    int c = egrp*32 + lane;
    int b = c >> 11;
    int e = c & (Eq-1);
    int t0 = chunk * CT;

    float Aen[Nq];
    #pragma unroll
    for (int n = 0; n < Nq; n++)
        Aen[n] = -__expf(A_log[e*Nq + n]) * LOG2E;
    float De = Dv[e];

    float h[Nq];
    const float4* hi = (const float4*)(g_hin + ((size_t)chunk*NCHAN + c)*Nq);
    #pragma unroll
    for (int q = 0; q < 4; q++) {
        float4 v = hi[q];
        h[q*4] = v.x; h[q*4+1] = v.y; h[q*4+2] = v.z; h[q*4+3] = v.w;
    }

    const float*  dp = g_delta + ((size_t)b*Lq + t0)*Eq + e;
    const __half* up = g_u     + ((size_t)b*Lq + t0)*Eq + e;
    const __half* gp = g_gate  + ((size_t)b*Lq + t0)*Eq + e;
    __half*       yp = g_y     + ((size_t)b*Lq + t0)*Eq + e;

    #pragma unroll 2
    for (int t = 0; t < CT; t++) {
        float d  = dp[(size_t)t*Eq];
        float xv = __half2float(up[(size_t)t*Eq]);
        float dx = d * xv;
        const float4* pB4 = (const float4*)(g_P + ((size_t)b*Lq + t0 + t)*PC + 64);
        float y = 0.f;
        #pragma unroll
        for (int q = 0; q < 4; q++) {
            float4 Bv = __ldg(pB4 + q);
            float4 Cv = __ldg(pB4 + 4 + q);
            float bb[4] = {Bv.x, Bv.y, Bv.z, Bv.w};
            float cc[4] = {Cv.x, Cv.y, Cv.z, Cv.w};
            #pragma unroll
            for (int r = 0; r < 4; r++) {
                int n = q*4 + r;
                float da = exp2f(d * Aen[n]);
                h[n] = fmaf(da, h[n], dx * bb[r]);
                y = fmaf(cc[r], h[n], y);
            }
        }
        float g = __half2float(gp[(size_t)t*Eq]);
        yp[(size_t)t*Eq] = __float2half_rn(fmaf(xv, De, y) * g);
    }
}

// ---------------- launch ----------------
extern "C" void kernel_launch(void* const* d_in, const int* in_sizes, int n_in,
                              void* d_out, int out_size) {
    const float* x       = (const float*)d_in[0];
    const float* lng     = (const float*)d_in[1];
    const float* lnb     = (const float*)d_in[2];
    const float* W_in    = (const float*)d_in[3];
    const float* b_in    = (const float*)d_in[4];
    const float* W_delta = (const float*)d_in[5];
    const float* b_delta = (const float*)d_in[6];
    const float* W_dt    = (const float*)d_in[7];
    const float* b_dt    = (const float*)d_in[8];
    const float* W_B     = (const float*)d_in[9];
    const float* b_B     = (const float*)d_in[10];
    const float* W_C     = (const float*)d_in[11];
    const float* b_C     = (const float*)d_in[12];
    const float* A_log   = (const float*)d_in[13];
    const float* Dv      = (const float*)d_in[14];
    const float* W_out   = (const float*)d_in[15];
    const float* b_out   = (const float*)d_in[16];
    float* out = (float*)d_out;

    void *p_xn, *p_u, *p_gate, *p_P, *p_Ph, *p_Ppart, *p_delta, *p_y;
    void *p_WcatT, *p_WtIn, *p_WtDt, *p_WtOut;
    cudaGetSymbolAddress(&p_xn,    g_xn);
    cudaGetSymbolAddress(&p_u,     g_u);
    cudaGetSymbolAddress(&p_gate,  g_gate);
    cudaGetSymbolAddress(&p_P,     g_P);
    cudaGetSymbolAddress(&p_Ph,    g_Ph);
    cudaGetSymbolAddress(&p_Ppart, g_Ppart);
    cudaGetSymbolAddress(&p_delta, g_delta);
    cudaGetSymbolAddress(&p_y,     g_y);
    cudaGetSymbolAddress(&p_WcatT, g_WcatT);
    cudaGetSymbolAddress(&p_WtIn,  g_WtIn);
    cudaGetSymbolAddress(&p_WtDt,  g_WtDt);
    cudaGetSymbolAddress(&p_WtOut, g_WtOut);

    static bool attr_done = false;
    if (!attr_done) {
        cudaFuncSetAttribute(gemm_h<EPI_SPLIT_SILU>, cudaFuncAttributeMaxDynamicSharedMemorySize, H_SMEM);
        cudaFuncSetAttribute(gemm_h<EPI_SOFTPLUS>,   cudaFuncAttributeMaxDynamicSharedMemorySize, H_SMEM);
        cudaFuncSetAttribute(gemm_h<EPI_RES>,        cudaFuncAttributeMaxDynamicSharedMemorySize, H_SMEM);
        cudaFuncSetAttribute(gemm_h<EPI_PART>,       cudaFuncAttributeMaxDynamicSharedMemorySize, H_SMEM);
        attr_done = true;
    }

    // prep: fp16 transposed weights + packed proj weight
    transpose_h<<<dim3(2*Eq/32, Hq/32), dim3(32,8)>>>(W_in,  (__half*)p_WtIn,  Hq, 2*Eq);
    transpose_h<<<dim3(Hq/32,   Eq/32), dim3(32,8)>>>(W_out, (__half*)p_WtOut, Eq, Hq);
    transpose_h<<<dim3(Eq/32,   Rq/32), dim3(32,8)>>>(W_dt,  (__half*)p_WtDt,  Rq, Eq);
    pack_kernel<<<(PCP*Eq + 255)/256, 256>>>(W_delta, W_B, W_C, b_delta, b_B, b_C);
    // LayerNorm -> fp16 xn
    ln_kernel<<<TOK, 256>>>(x, lng, lnb);
    // GEMM1: xn @ W_in -> silu(u), silu(gate)
    gemm_h<EPI_SPLIT_SILU><<<dim3(2*Eq/128, TOK/128), 256, H_SMEM>>>(
        (const __half*)p_xn, Hq, (const __half*)p_WtIn, Hq, b_in,
        p_u, Eq, nullptr, (__half*)p_gate, TOK, 2*Eq, Hq, Hq);
    // P partials = u @ Wcat (split-K), reduce (+fp16 copy of delta part)
    gemm_h<EPI_PART><<<dim3(1, TOK/128, KSPLIT), 256, H_SMEM>>>(
        (const __half*)p_u, Eq, (const __half*)p_WcatT, Eq, nullptr,
        p_Ppart, PC, nullptr, nullptr, TOK, PC, Eq, Eq/KSPLIT);
    reduceP_kernel<<<(TOK*PC + 255)/256, 256>>>();
    // delta = softplus(Ph @ W_dt)
    gemm_h<EPI_SOFTPLUS><<<dim3(Eq/128, TOK/128), 256, H_SMEM>>>(
        (const __half*)p_Ph, 64, (const __half*)p_WtDt, Rq, b_dt,
        p_delta, Eq, nullptr, nullptr, TOK, Eq, Rq, Rq);
    // chunked selective scan
    scan_p1<<<(NCHAN/32)*NCHUNK/8, 256>>>(A_log);
    scan_p2<<<(NCHAN*Nq + 255)/256, 256>>>();
    scan_p3<<<(NCHAN/32)*NCHUNK/8, 256>>>(A_log, Dv);
    // out = y @ W_out + b_out + residual
    gemm_h<EPI_RES><<<dim3(Hq/128, TOK/128), 256, H_SMEM>>>(
        (const __half*)p_y, Eq, (const __half*)p_WtOut, Eq, b_out,
        out, Hq, x, nullptr, TOK, Hq, Eq, Eq);
}

// round 12
// speedup vs baseline: 1.0077x; 1.0077x over previous
#include <cuda_runtime.h>
#include <cuda_fp16.h>
#include <math.h>
#include <stdint.h>

// Problem constants
#define Bq   2
#define Lq   2048
#define Hq   1024
#define Eq   2048
#define Nq   16
#define Rq   64
#define TOK  (Bq*Lq)        // 4096 tokens
#define PC   96             // packed proj cols: 64 (delta) + 16 (B) + 16 (C)
#define PCP  128            // padded N for P-GEMM
#define KSPLIT 8
#define NCHUNK 32           // scan chunks
#define CT    (Lq/NCHUNK)   // 64 timesteps per chunk
#define NCHAN (Bq*Eq)       // 4096 channels

// ---------------- device scratch (allocation-free) ----------------
__device__ __align__(16) __half g_xn[TOK*Hq];      // layernormed input (fp16)
__device__ __align__(16) __half g_u[TOK*Eq];       // silu(u) fp16
__device__ __align__(16) __half g_gate[TOK*Eq];    // silu(gate) fp16
__device__ __align__(16) __half g_y[TOK*Eq];       // scan output fp16
__device__ __align__(16) float  g_P[TOK*PC];       // [delta_proj(64) | B(16) | C(16)] f32
__device__ __align__(16) __half g_Ph[TOK*64];      // delta-proj part, fp16 (GEMM input)
__device__ __align__(16) float  g_Ppart[KSPLIT*TOK*PC];
__device__ __align__(16) float  g_delta[TOK*Eq];   // softplus delta f32
__device__ __align__(16) __half g_WcatT[PCP*Eq];   // [delta|B|C]^T padded, fp16
__device__ float g_bcat[PC];
__device__ __align__(16) __half g_WtIn[2*Eq*Hq];   // W_in^T  [4096][1024] fp16
__device__ __align__(16) __half g_WtDt[Eq*Rq];     // W_dt^T  [2048][64]   fp16
__device__ __align__(16) __half g_WtOut[Hq*Eq];    // W_out^T [1024][2048] fp16
// chunked-scan state: [chunk][chan][n]
__device__ __align__(16) float g_ap [NCHUNK*NCHAN*Nq];
__device__ __align__(16) float g_c  [NCHUNK*NCHAN*Nq];
__device__ __align__(16) float g_hin[NCHUNK*NCHAN*Nq];

__device__ __forceinline__ uint32_t sptr(const void* p) {
    return (uint32_t)__cvta_generic_to_shared(p);
}

// ---------------- LayerNorm (writes fp16 xn) ----------------
__global__ void ln_kernel(const float* __restrict__ x,
                          const float* __restrict__ gamma,
                          const float* __restrict__ beta) {
    int m = blockIdx.x;
    const float* row = x + (size_t)m*Hq;
    float s = 0.f, s2 = 0.f;
    for (int i = threadIdx.x; i < Hq; i += blockDim.x) {
        float v = row[i]; s += v; s2 += v*v;
    }
    __shared__ float sh[64];
    for (int o = 16; o; o >>= 1) {
        s  += __shfl_xor_sync(~0u, s,  o);
        s2 += __shfl_xor_sync(~0u, s2, o);
    }
    int wid = threadIdx.x >> 5, lane = threadIdx.x & 31;
    if (lane == 0) { sh[wid] = s; sh[32+wid] = s2; }
    __syncthreads();
    if (wid == 0) {
        int nw = blockDim.x >> 5;
        s  = (lane < nw) ? sh[lane]    : 0.f;
        s2 = (lane < nw) ? sh[32+lane] : 0.f;
        for (int o = 16; o; o >>= 1) {
            s  += __shfl_xor_sync(~0u, s,  o);
            s2 += __shfl_xor_sync(~0u, s2, o);
        }
        if (lane == 0) { sh[0] = s; sh[1] = s2; }
    }
    __syncthreads();
    float mu  = sh[0] * (1.f/Hq);
    float var = sh[1] * (1.f/Hq) - mu*mu;
    float inv = rsqrtf(var + 1e-5f);
    for (int i = threadIdx.x; i < Hq; i += blockDim.x) {
        g_xn[(size_t)m*Hq + i] = __float2half_rn((row[i]-mu)*inv*gamma[i] + beta[i]);
    }
}

// ---------------- tiled transpose to fp16: dst[c][r] = h(src[r][c]) ----------
__global__ void transpose_h(const float* __restrict__ src, __half* __restrict__ dst,
                            int R, int Cc) {
    __shared__ float t[32][33];
    int c0 = blockIdx.x*32, r0 = blockIdx.y*32;
    for (int i = threadIdx.y; i < 32; i += 8)
        t[i][threadIdx.x] = src[(size_t)(r0+i)*Cc + c0 + threadIdx.x];
    __syncthreads();
    for (int i = threadIdx.y; i < 32; i += 8)
        dst[(size_t)(c0+i)*R + r0 + threadIdx.x] = __float2half_rn(t[threadIdx.x][i]);
}

// ---------------- pack W_delta|W_B|W_C transposed+padded, fp16 --------------
__global__ void pack_kernel(const float* __restrict__ Wd, const float* __restrict__ Wb,
                            const float* __restrict__ Wc, const float* __restrict__ bd,
                            const float* __restrict__ bb, const float* __restrict__ bc) {
    int i = blockIdx.x*blockDim.x + threadIdx.x;
    if (i < PCP*Eq) {
        int c = i / Eq, k = i % Eq;
        float v = 0.f;
        if (c < 64)      v = Wd[k*64 + c];
        else if (c < 80) v = Wb[k*16 + (c-64)];
        else if (c < 96) v = Wc[k*16 + (c-80)];
        g_WcatT[i] = __float2half_rn(v);
    }
    if (i < PC) {
        g_bcat[i] = (i < 64) ? bd[i] : ((i < 80) ? bb[i-64] : bc[i-80]);
    }
}

// ---------------- split-K reduction for P (f32 + fp16 delta part) -----------
__global__ void reduceP_kernel() {
    int i = blockIdx.x*blockDim.x + threadIdx.x;
    if (i >= TOK*PC) return;
    int c = i % PC, m = i / PC;
    float s = g_bcat[c];
    #pragma unroll
    for (int z = 0; z < KSPLIT; z++) s += g_Ppart[(size_t)z*TOK*PC + i];
    g_P[i] = s;
    if (c < 64) g_Ph[(size_t)m*64 + c] = __float2half_rn(s);
}

// ======== fp16 m16n8k16 GEMM, 8 warps, 64x32 warptiles, ldmatrix ============
enum { EPI_SPLIT_SILU = 1, EPI_SOFTPLUS = 2, EPI_RES = 3, EPI_PART = 4 };

#define MMA_F16(c0,c1,c2,c3,a0,a1,a2,a3,b0,b1) \
    asm volatile("mma.sync.aligned.m16n8k16.row.col.f32.f16.f16.f32 " \
                 "{%0,%1,%2,%3},{%4,%5,%6,%7},{%8,%9},{%0,%1,%2,%3};" \
                 : "+f"(c0),"+f"(c1),"+f"(c2),"+f"(c3) \
                 : "r"(a0),"r"(a1),"r"(a2),"r"(a3),"r"(b0),"r"(b1))

#define LDSM_X4(r0,r1,r2,r3,addr) \
    asm volatile("ldmatrix.sync.aligned.m8n8.x4.shared.b16 {%0,%1,%2,%3}, [%4];" \
                 : "=r"(r0),"=r"(r1),"=r"(r2),"=r"(r3) : "r"(addr))

template<int N> __device__ __forceinline__ void cp_wait() {
    asm volatile("cp.async.wait_group %0;" :: "n"(N));
}
__device__ __forceinline__ void cp_commit() {
    asm volatile("cp.async.commit_group;" ::);
}

#define HBM 128
#define HBN 128
#define HBK 32
#define HSTAGE 4
#define HLD 40                      // halves per row (32 + 8 pad) = 80 bytes
#define HSTG (HBM*HLD)              // halves per stage tile (5120)
#define H_SMEM (HSTAGE*HSTG*2*2)    // A + B regions, bytes (81920)

template<int EPI>
__global__ void __launch_bounds__(256, 2)
gemm_h(const __half* __restrict__ A, int lda,
       const __half* __restrict__ Bt, int ldb,    // [N][K] K-major
       const float* __restrict__ bias,
       void* __restrict__ Cv, int ldc,
       const float* __restrict__ resid,           // residual (RES)
       __half* __restrict__ gate,                 // gate out (SPLIT_SILU)
       int M, int N, int K, int Kchunk)
{
    extern __shared__ __half smh[];
    __half* Asm = smh;
    __half* Bsm = smh + HSTAGE*HSTG;
    const uint32_t aBase = sptr(Asm);
    const uint32_t bBase = sptr(Bsm);

    const int tid  = threadIdx.x;
    const int lane = tid & 31;
    const int warp = tid >> 5;
    const int wr   = warp & 1;          // 2 x 64 rows
    const int wc   = warp >> 1;         // 4 x 32 cols
    const int m0   = blockIdx.y * HBM;
    const int n0   = blockIdx.x * HBN;
    const int Koff = blockIdx.z * Kchunk;

    // ldmatrix per-lane base offsets (halves; *2 for bytes at use site)
    const uint32_t aRow = wr*64 + (lane & 15);
    const uint32_t aCol = (lane >> 4) * 8;
    // B non-trans: lanes 0-7 rows n0..7 @k0 | 8-15 @k0+8 | 16-23 rows n8..15 @k0 | 24-31 @k0+8
    const uint32_t bRow = wc*32 + (lane & 7) + ((lane >> 4) << 3);
    const uint32_t bCol = ((lane >> 3) & 1) * 8;

    auto issue = [&](int it, int buf) {
        int k0 = Koff + it * HBK;
        #pragma unroll
        for (int j = 0; j < 2; j++) {
            int id = tid + j*256;
            int row = id >> 2, slot = id & 3;
            const __half* as = A  + (size_t)(m0 + row)*lda + k0 + slot*8;
            const __half* bs = Bt + (size_t)(n0 + row)*ldb + k0 + slot*8;
            asm volatile("cp.async.ca.shared.global [%0], [%1], 16;\n"
                         :: "r"(aBase + buf*(HSTG*2) + row*80 + slot*16), "l"(as));
            asm volatile("cp.async.ca.shared.global [%0], [%1], 16;\n"
                         :: "r"(bBase + buf*(HSTG*2) + row*80 + slot*16), "l"(bs));
        }
    };

    float acc[4][4][4];
    #pragma unroll
    for (int i = 0; i < 4; i++)
        #pragma unroll
        for (int j = 0; j < 4; j++)
            #pragma unroll
            for (int k = 0; k < 4; k++) acc[i][j][k] = 0.f;

    const int nIter = Kchunk / HBK;
    #pragma unroll
    for (int s = 0; s < HSTAGE-1; s++) {
        if (s < nIter) issue(s, s);
        cp_commit();
    }

    for (int it = 0; it < nIter; it++) {
        cp_wait<HSTAGE-2>();
        __syncthreads();
        int nx = it + HSTAGE - 1;
        if (nx < nIter) issue(nx, nx & (HSTAGE-1));
        cp_commit();

        int buf = it & (HSTAGE-1);
        uint32_t aB = aBase + buf*(HSTG*2);
        uint32_t bB = bBase + buf*(HSTG*2);

        #pragma unroll
        for (int kk = 0; kk < 2; kk++) {
            uint32_t af[4][4], bf[4][2];
            #pragma unroll
            for (int mt = 0; mt < 4; mt++) {
                uint32_t ad = aB + ((aRow + mt*16)*HLD + kk*16 + aCol)*2;
                LDSM_X4(af[mt][0], af[mt][1], af[mt][2], af[mt][3], ad);
            }
            #pragma unroll
            for (int ntp = 0; ntp < 2; ntp++) {
                uint32_t bd = bB + ((bRow + ntp*16)*HLD + kk*16 + bCol)*2;
                LDSM_X4(bf[2*ntp][0], bf[2*ntp][1], bf[2*ntp+1][0], bf[2*ntp+1][1], bd);
            }
            #pragma unroll
            for (int mt = 0; mt < 4; mt++)
                #pragma unroll
                for (int nt = 0; nt < 4; nt++)
                    MMA_F16(acc[mt][nt][0], acc[mt][nt][1], acc[mt][nt][2], acc[mt][nt][3],
                            af[mt][0], af[mt][1], af[mt][2], af[mt][3],
                            bf[nt][0], bf[nt][1]);
        }
    }

    // epilogue: pair (q0,q1)/(q2,q3) -> column-adjacent vector stores
    #pragma unroll
    for (int mt = 0; mt < 4; mt++) {
        #pragma unroll
        for (int nt = 0; nt < 4; nt++) {
            #pragma unroll
            for (int half = 0; half < 2; half++) {
                int gm = m0 + wr*64 + mt*16 + (lane >> 2) + half*8;
                int gn = n0 + wc*32 + nt*8 + 2*(lane & 3);
                float v0 = acc[mt][nt][half*2 + 0];
                float v1 = acc[mt][nt][half*2 + 1];
                if (EPI == EPI_PART) {
                    if (gn < N) {
                        float* dst = (float*)Cv + (size_t)blockIdx.z*TOK*PC + (size_t)gm*ldc + gn;
                        dst[0] = v0;
                        if (gn + 1 < N) dst[1] = v1;
                    }
                    continue;
                }
                v0 += bias[gn]; v1 += bias[gn+1];
                if (EPI == EPI_SPLIT_SILU) {
                    float s0 = v0 / (1.f + __expf(-v0));
                    float s1 = v1 / (1.f + __expf(-v1));
                    __half2 hv = __floats2half2_rn(s0, s1);
                    if (gn < Eq) *(__half2*)((__half*)Cv + (size_t)gm*Eq + gn) = hv;
                    else         *(__half2*)(gate + (size_t)gm*Eq + gn - Eq)  = hv;
                } else if (EPI == EPI_SOFTPLUS) {
                    float2 f2;
                    f2.x = (v0 > 20.f) ? v0 : log1pf(__expf(v0));
                    f2.y = (v1 > 20.f) ? v1 : log1pf(__expf(v1));
                    *(float2*)((float*)Cv + (size_t)gm*ldc + gn) = f2;
                } else { // EPI_RES
                    const float2 r2 = *(const float2*)(resid + (size_t)gm*ldc + gn);
                    float2 f2; f2.x = v0 + r2.x; f2.y = v1 + r2.y;
                    *(float2*)((float*)Cv + (size_t)gm*ldc + gn) = f2;
                }
            }
        }
    }
}

// ---------------- chunked selective scan ----------------
#define LOG2E 1.4426950408889634f

__global__ void __launch_bounds__(256)
scan_p1(const float* __restrict__ A_log) {
    int gw    = blockIdx.x*8 + (threadIdx.x >> 5);
    int lane  = threadIdx.x & 31;
    int egrp  = gw & 127;
    int chunk = gw >> 7;
    int c = egrp*32 + lane;
    int b = c >> 11;
    int e = c & (Eq-1);
    int t0 = chunk * CT;

    float Aen[Nq];
    #pragma unroll
    for (int n = 0; n < Nq; n++)
        Aen[n] = -__expf(A_log[e*Nq + n]) * LOG2E;

    float h[Nq], ap[Nq];
    #pragma unroll
    for (int n = 0; n < Nq; n++) { h[n] = 0.f; ap[n] = 1.f; }

    const float*  dp = g_delta + ((size_t)b*Lq + t0)*Eq + e;
    const __half* up = g_u     + ((size_t)b*Lq + t0)*Eq + e;

    #pragma unroll 2
    for (int t = 0; t < CT; t++) {
        float d  = dp[(size_t)t*Eq];
        float xv = __half2float(up[(size_t)t*Eq]);
        float dx = d * xv;
        const float4* pB4 = (const float4*)(g_P + ((size_t)b*Lq + t0 + t)*PC + 64);
        #pragma unroll
        for (int q = 0; q < 4; q++) {
            float4 Bv = __ldg(pB4 + q);
            float bb[4] = {Bv.x, Bv.y, Bv.z, Bv.w};
            #pragma unroll
            for (int r = 0; r < 4; r++) {
                int n = q*4 + r;
                float da = exp2f(d * Aen[n]);
                ap[n] *= da;
                h[n] = fmaf(da, h[n], dx * bb[r]);
            }
        }
    }
    float4* apo = (float4*)(g_ap + ((size_t)chunk*NCHAN + c)*Nq);
    float4* co  = (float4*)(g_c  + ((size_t)chunk*NCHAN + c)*Nq);
    #pragma unroll
    for (int q = 0; q < 4; q++) {
        apo[q] = make_float4(ap[q*4], ap[q*4+1], ap[q*4+2], ap[q*4+3]);
        co[q]  = make_float4(h[q*4],  h[q*4+1],  h[q*4+2],  h[q*4+3]);
    }
}

__global__ void __launch_bounds__(256)
scan_p2() {
    int i = blockIdx.x*blockDim.x + threadIdx.x;
    if (i >= NCHAN*Nq) return;
    float hin = 0.f;
    #pragma unroll
    for (int k = 0; k < NCHUNK; k++) {
        size_t idx = (size_t)k*NCHAN*Nq + i;
        g_hin[idx] = hin;
        hin = g_ap[idx]*hin + g_c[idx];
    }
}

__global__ void __launch_bounds__(256)
scan_p3(const float* __restrict__ A_log, const float* __restrict__ Dv) {
    int gw    = blockIdx.x*8 + (threadIdx.x >> 5);
    int lane  = threadIdx.x & 31;
    int egrp  = gw & 127;
    int chunk = gw >> 7;
    int c = egrp*32 + lane;
    int b = c >> 11;
    int e = c & (Eq-1);
    int t0 = chunk * CT;

    float Aen[Nq];
    #pragma unroll
    for (int n = 0; n < Nq; n++)
        Aen[n] = -__expf(A_log[e*Nq + n]) * LOG2E;
    float De = Dv[e];

    float h[Nq];
    const float4* hi = (const float4*)(g_hin + ((size_t)chunk*NCHAN + c)*Nq);
    #pragma unroll
    for (int q = 0; q < 4; q++) {
        float4 v = hi[q];
        h[q*4] = v.x; h[q*4+1] = v.y; h[q*4+2] = v.z; h[q*4+3] = v.w;
    }

    const float*  dp = g_delta + ((size_t)b*Lq + t0)*Eq + e;
    const __half* up = g_u     + ((size_t)b*Lq + t0)*Eq + e;
    const __half* gp = g_gate  + ((size_t)b*Lq + t0)*Eq + e;
    __half*       yp = g_y     + ((size_t)b*Lq + t0)*Eq + e;

    #pragma unroll 2
    for (int t = 0; t < CT; t++) {
        float d  = dp[(size_t)t*Eq];
        float xv = __half2float(up[(size_t)t*Eq]);
        float dx = d * xv;
        const float4* pB4 = (const float4*)(g_P + ((size_t)b*Lq + t0 + t)*PC + 64);
        float y = 0.f;
        #pragma unroll
        for (int q = 0; q < 4; q++) {
            float4 Bv = __ldg(pB4 + q);
            float4 Cv = __ldg(pB4 + 4 + q);
            float bb[4] = {Bv.x, Bv.y, Bv.z, Bv.w};
            float cc[4] = {Cv.x, Cv.y, Cv.z, Cv.w};
            #pragma unroll
            for (int r = 0; r < 4; r++) {
                int n = q*4 + r;
                float da = exp2f(d * Aen[n]);
                h[n] = fmaf(da, h[n], dx * bb[r]);
                y = fmaf(cc[r], h[n], y);
            }
        }
        float g = __half2float(gp[(size_t)t*Eq]);
        yp[(size_t)t*Eq] = __float2half_rn(fmaf(xv, De, y) * g);
    }
}

// ---------------- launch ----------------
extern "C" void kernel_launch(void* const* d_in, const int* in_sizes, int n_in,
                              void* d_out, int out_size) {
    const float* x       = (const float*)d_in[0];
    const float* lng     = (const float*)d_in[1];
    const float* lnb     = (const float*)d_in[2];
    const float* W_in    = (const float*)d_in[3];
    const float* b_in    = (const float*)d_in[4];
    const float* W_delta = (const float*)d_in[5];
    const float* b_delta = (const float*)d_in[6];
    const float* W_dt    = (const float*)d_in[7];
    const float* b_dt    = (const float*)d_in[8];
    const float* W_B     = (const float*)d_in[9];
    const float* b_B     = (const float*)d_in[10];
    const float* W_C     = (const float*)d_in[11];
    const float* b_C     = (const float*)d_in[12];
    const float* A_log   = (const float*)d_in[13];
    const float* Dv      = (const float*)d_in[14];
    const float* W_out   = (const float*)d_in[15];
    const float* b_out   = (const float*)d_in[16];
    float* out = (float*)d_out;

    void *p_xn, *p_u, *p_gate, *p_P, *p_Ph, *p_Ppart, *p_delta, *p_y;
    void *p_WcatT, *p_WtIn, *p_WtDt, *p_WtOut;
    cudaGetSymbolAddress(&p_xn,    g_xn);
    cudaGetSymbolAddress(&p_u,     g_u);
    cudaGetSymbolAddress(&p_gate,  g_gate);
    cudaGetSymbolAddress(&p_P,     g_P);
    cudaGetSymbolAddress(&p_Ph,    g_Ph);
    cudaGetSymbolAddress(&p_Ppart, g_Ppart);
    cudaGetSymbolAddress(&p_delta, g_delta);
    cudaGetSymbolAddress(&p_y,     g_y);
    cudaGetSymbolAddress(&p_WcatT, g_WcatT);
    cudaGetSymbolAddress(&p_WtIn,  g_WtIn);
    cudaGetSymbolAddress(&p_WtDt,  g_WtDt);
    cudaGetSymbolAddress(&p_WtOut, g_WtOut);

    static bool attr_done = false;
    if (!attr_done) {
        cudaFuncSetAttribute(gemm_h<EPI_SPLIT_SILU>, cudaFuncAttributeMaxDynamicSharedMemorySize, H_SMEM);
        cudaFuncSetAttribute(gemm_h<EPI_SOFTPLUS>,   cudaFuncAttributeMaxDynamicSharedMemorySize, H_SMEM);
        cudaFuncSetAttribute(gemm_h<EPI_RES>,        cudaFuncAttributeMaxDynamicSharedMemorySize, H_SMEM);
        cudaFuncSetAttribute(gemm_h<EPI_PART>,       cudaFuncAttributeMaxDynamicSharedMemorySize, H_SMEM);
        attr_done = true;
    }

    // prep: fp16 transposed weights + packed proj weight
    transpose_h<<<dim3(2*Eq/32, Hq/32), dim3(32,8)>>>(W_in,  (__half*)p_WtIn,  Hq, 2*Eq);
    transpose_h<<<dim3(Hq/32,   Eq/32), dim3(32,8)>>>(W_out, (__half*)p_WtOut, Eq, Hq);
    transpose_h<<<dim3(Eq/32,   Rq/32), dim3(32,8)>>>(W_dt,  (__half*)p_WtDt,  Rq, Eq);
    pack_kernel<<<(PCP*Eq + 255)/256, 256>>>(W_delta, W_B, W_C, b_delta, b_B, b_C);
    // LayerNorm -> fp16 xn
    ln_kernel<<<TOK, 256>>>(x, lng, lnb);
    // GEMM1: xn @ W_in -> silu(u), silu(gate)
    gemm_h<EPI_SPLIT_SILU><<<dim3(2*Eq/128, TOK/128), 256, H_SMEM>>>(
        (const __half*)p_xn, Hq, (const __half*)p_WtIn, Hq, b_in,
        p_u, Eq, nullptr, (__half*)p_gate, TOK, 2*Eq, Hq, Hq);
    // P partials = u @ Wcat (split-K), reduce (+fp16 copy of delta part)
    gemm_h<EPI_PART><<<dim3(1, TOK/128, KSPLIT), 256, H_SMEM>>>(
        (const __half*)p_u, Eq, (const __half*)p_WcatT, Eq, nullptr,
        p_Ppart, PC, nullptr, nullptr, TOK, PC, Eq, Eq/KSPLIT);
    reduceP_kernel<<<(TOK*PC + 255)/256, 256>>>();
    // delta = softplus(Ph @ W_dt)
    gemm_h<EPI_SOFTPLUS><<<dim3(Eq/128, TOK/128), 256, H_SMEM>>>(
        (const __half*)p_Ph, 64, (const __half*)p_WtDt, Rq, b_dt,
        p_delta, Eq, nullptr, nullptr, TOK, Eq, Rq, Rq);
    // chunked selective scan
    scan_p1<<<(NCHAN/32)*NCHUNK/8, 256>>>(A_log);
    scan_p2<<<(NCHAN*Nq + 255)/256, 256>>>();
    scan_p3<<<(NCHAN/32)*NCHUNK/8, 256>>>(A_log, Dv);
    // out = y @ W_out + b_out + residual
    gemm_h<EPI_RES><<<dim3(Hq/128, TOK/128), 256, H_SMEM>>>(
        (const __half*)p_y, Eq, (const __half*)p_WtOut, Eq, b_out,
        out, Hq, x, nullptr, TOK, Hq, Eq, Eq);
}

// round 13
// speedup vs baseline: 1.0916x; 1.0833x over previous
#include <cuda_runtime.h>
#include <cuda_fp16.h>
#include <math.h>
#include <stdint.h>

// Problem constants
#define Bq   2
#define Lq   2048
#define Hq   1024
#define Eq   2048
#define Nq   16
#define Rq   64
#define TOK  (Bq*Lq)        // 4096 tokens
#define PC   96             // packed proj cols: 64 (delta) + 16 (B) + 16 (C)
#define PCP  128            // padded N for P-GEMM
#define KSPLIT 8
#define NCHUNK 32           // scan chunks
#define CT    (Lq/NCHUNK)   // 64 timesteps per chunk
#define NCHAN (Bq*Eq)       // 4096 channels

// ---------------- device scratch (allocation-free) ----------------
__device__ __align__(16) __half g_xn[TOK*Hq];      // layernormed input (fp16)
__device__ __align__(16) __half g_u[TOK*Eq];       // silu(u) fp16
__device__ __align__(16) __half g_gate[TOK*Eq];    // silu(gate) fp16
__device__ __align__(16) __half g_y[TOK*Eq];       // scan output fp16
__device__ __align__(16) float  g_P[TOK*PC];       // [delta_proj(64) | B(16) | C(16)] f32
__device__ __align__(16) __half g_Ph[TOK*64];      // delta-proj part, fp16 (GEMM input)
__device__ __align__(16) float  g_Ppart[KSPLIT*TOK*PC];
__device__ __align__(16) __half g_delta[TOK*Eq];   // softplus delta fp16
__device__ __align__(16) __half g_WcatT[PCP*Eq];   // [delta|B|C]^T padded, fp16
__device__ float g_bcat[PC];
__device__ __align__(16) __half g_WtIn[2*Eq*Hq];   // W_in^T  [4096][1024] fp16
__device__ __align__(16) __half g_WtDt[Eq*Rq];     // W_dt^T  [2048][64]   fp16
__device__ __align__(16) __half g_WtOut[Hq*Eq];    // W_out^T [1024][2048] fp16
// chunked-scan state: [chunk][chan][n]
__device__ __align__(16) float g_ap [NCHUNK*NCHAN*Nq];
__device__ __align__(16) float g_c  [NCHUNK*NCHAN*Nq];
__device__ __align__(16) float g_hin[NCHUNK*NCHAN*Nq];

__device__ __forceinline__ uint32_t sptr(const void* p) {
    return (uint32_t)__cvta_generic_to_shared(p);
}

// ---------------- LayerNorm (writes fp16 xn) ----------------
__global__ void ln_kernel(const float* __restrict__ x,
                          const float* __restrict__ gamma,
                          const float* __restrict__ beta) {
    int m = blockIdx.x;
    const float* row = x + (size_t)m*Hq;
    float s = 0.f, s2 = 0.f;
    for (int i = threadIdx.x; i < Hq; i += blockDim.x) {
        float v = row[i]; s += v; s2 += v*v;
    }
    __shared__ float sh[64];
    for (int o = 16; o; o >>= 1) {
        s  += __shfl_xor_sync(~0u, s,  o);
        s2 += __shfl_xor_sync(~0u, s2, o);
    }
    int wid = threadIdx.x >> 5, lane = threadIdx.x & 31;
    if (lane == 0) { sh[wid] = s; sh[32+wid] = s2; }
    __syncthreads();
    if (wid == 0) {
        int nw = blockDim.x >> 5;
        s  = (lane < nw) ? sh[lane]    : 0.f;
        s2 = (lane < nw) ? sh[32+lane] : 0.f;
        for (int o = 16; o; o >>= 1) {
            s  += __shfl_xor_sync(~0u, s,  o);
            s2 += __shfl_xor_sync(~0u, s2, o);
        }
        if (lane == 0) { sh[0] = s; sh[1] = s2; }
    }
    __syncthreads();
    float mu  = sh[0] * (1.f/Hq);
    float var = sh[1] * (1.f/Hq) - mu*mu;
    float inv = rsqrtf(var + 1e-5f);
    for (int i = threadIdx.x; i < Hq; i += blockDim.x) {
        g_xn[(size_t)m*Hq + i] = __float2half_rn((row[i]-mu)*inv*gamma[i] + beta[i]);
    }
}

// ---------------- fused prep: 3 transposes + pack, one launch ----------------
// block ranges: [0,4096) t_in | [4096,6144) t_out | [6144,6272) t_dt | [6272,7296) pack
#define PREP_BLOCKS 7296
__global__ void prep_kernel(const float* __restrict__ W_in,
                            const float* __restrict__ W_out,
                            const float* __restrict__ W_dt,
                            const float* __restrict__ Wd, const float* __restrict__ Wb,
                            const float* __restrict__ Wc, const float* __restrict__ bd,
                            const float* __restrict__ bb, const float* __restrict__ bc) {
    int blk = blockIdx.x;
    if (blk < 6272) {
        // tiled transpose: dst[c][r] = h(src[r][c])
        const float* src; __half* dst; int R, Cc, bx, nbx;
        if (blk < 4096)      { src = W_in;  dst = g_WtIn;  R = Hq; Cc = 2*Eq; bx = blk;        nbx = 2*Eq/32; }
        else if (blk < 6144) { src = W_out; dst = g_WtOut; R = Eq; Cc = Hq;   bx = blk - 4096; nbx = Hq/32; }
        else                 { src = W_dt;  dst = g_WtDt;  R = Rq; Cc = Eq;   bx = blk - 6144; nbx = Eq/32; }
        int c0 = (bx % nbx) * 32, r0 = (bx / nbx) * 32;
        int tx = threadIdx.x & 31, ty = threadIdx.x >> 5;
        __shared__ float t[32][33];
        for (int i = ty; i < 32; i += 8)
            t[i][tx] = src[(size_t)(r0+i)*Cc + c0 + tx];
        __syncthreads();
        for (int i = ty; i < 32; i += 8)
            dst[(size_t)(c0+i)*R + r0 + tx] = __float2half_rn(t[tx][i]);
    } else {
        int i = (blk - 6272)*256 + threadIdx.x;
        if (i < PCP*Eq) {
            int c = i / Eq, k = i % Eq;
            float v = 0.f;
            if (c < 64)      v = Wd[k*64 + c];
            else if (c < 80) v = Wb[k*16 + (c-64)];
            else if (c < 96) v = Wc[k*16 + (c-80)];
            g_WcatT[i] = __float2half_rn(v);
        }
        if (i < PC) {
            g_bcat[i] = (i < 64) ? bd[i] : ((i < 80) ? bb[i-64] : bc[i-80]);
        }
    }
}

// ---------------- split-K reduction for P (f32 + fp16 delta part) -----------
__global__ void reduceP_kernel() {
    int i = blockIdx.x*blockDim.x + threadIdx.x;
    if (i >= TOK*PC) return;
    int c = i % PC, m = i / PC;
    float s = g_bcat[c];
    #pragma unroll
    for (int z = 0; z < KSPLIT; z++) s += g_Ppart[(size_t)z*TOK*PC + i];
    g_P[i] = s;
    if (c < 64) g_Ph[(size_t)m*64 + c] = __float2half_rn(s);
}

// ======== fp16 m16n8k16 GEMM, 8 warps, 64x32 warptiles, ldmatrix ============
enum { EPI_SPLIT_SILU = 1, EPI_SOFTPLUS = 2, EPI_RES = 3, EPI_PART = 4 };

#define MMA_F16(c0,c1,c2,c3,a0,a1,a2,a3,b0,b1) \
    asm volatile("mma.sync.aligned.m16n8k16.row.col.f32.f16.f16.f32 " \
                 "{%0,%1,%2,%3},{%4,%5,%6,%7},{%8,%9},{%0,%1,%2,%3};" \
                 : "+f"(c0),"+f"(c1),"+f"(c2),"+f"(c3) \
                 : "r"(a0),"r"(a1),"r"(a2),"r"(a3),"r"(b0),"r"(b1))

#define LDSM_X4(r0,r1,r2,r3,addr) \
    asm volatile("ldmatrix.sync.aligned.m8n8.x4.shared.b16 {%0,%1,%2,%3}, [%4];" \
                 : "=r"(r0),"=r"(r1),"=r"(r2),"=r"(r3) : "r"(addr))

template<int N> __device__ __forceinline__ void cp_wait() {
    asm volatile("cp.async.wait_group %0;" :: "n"(N));
}
__device__ __forceinline__ void cp_commit() {
    asm volatile("cp.async.commit_group;" ::);
}

#define HBM 128
#define HBN 128
#define HBK 32
#define HSTAGE 4
#define HLD 40                      // halves per row (32 + 8 pad) = 80 bytes
#define HSTG (HBM*HLD)              // halves per stage tile (5120)
#define H_SMEM (HSTAGE*HSTG*2*2)    // A + B regions, bytes (81920)

template<int EPI>
__global__ void __launch_bounds__(256, 2)
gemm_h(const __half* __restrict__ A, int lda,
       const __half* __restrict__ Bt, int ldb,    // [N][K] K-major
       const float* __restrict__ bias,
       void* __restrict__ Cv, int ldc,
       const float* __restrict__ resid,           // residual (RES)
       __half* __restrict__ gate,                 // gate out (SPLIT_SILU)
       int M, int N, int K, int Kchunk)
{
    extern __shared__ __half smh[];
    __half* Asm = smh;
    __half* Bsm = smh + HSTAGE*HSTG;
    const uint32_t aBase = sptr(Asm);
    const uint32_t bBase = sptr(Bsm);

    const int tid  = threadIdx.x;
    const int lane = tid & 31;
    const int warp = tid >> 5;
    const int wr   = warp & 1;          // 2 x 64 rows
    const int wc   = warp >> 1;         // 4 x 32 cols
    const int m0   = blockIdx.y * HBM;
    const int n0   = blockIdx.x * HBN;
    const int Koff = blockIdx.z * Kchunk;

    const uint32_t aRow = wr*64 + (lane & 15);
    const uint32_t aCol = (lane >> 4) * 8;
    const uint32_t bRow = wc*32 + (lane & 7) + ((lane >> 4) << 3);
    const uint32_t bCol = ((lane >> 3) & 1) * 8;

    auto issue = [&](int it, int buf) {
        int k0 = Koff + it * HBK;
        #pragma unroll
        for (int j = 0; j < 2; j++) {
            int id = tid + j*256;
            int row = id >> 2, slot = id & 3;
            const __half* as = A  + (size_t)(m0 + row)*lda + k0 + slot*8;
            const __half* bs = Bt + (size_t)(n0 + row)*ldb + k0 + slot*8;
            asm volatile("cp.async.ca.shared.global [%0], [%1], 16;\n"
                         :: "r"(aBase + buf*(HSTG*2) + row*80 + slot*16), "l"(as));
            asm volatile("cp.async.ca.shared.global [%0], [%1], 16;\n"
                         :: "r"(bBase + buf*(HSTG*2) + row*80 + slot*16), "l"(bs));
        }
    };

    float acc[4][4][4];
    #pragma unroll
    for (int i = 0; i < 4; i++)
        #pragma unroll
        for (int j = 0; j < 4; j++)
            #pragma unroll
            for (int k = 0; k < 4; k++) acc[i][j][k] = 0.f;

    const int nIter = Kchunk / HBK;
    #pragma unroll
    for (int s = 0; s < HSTAGE-1; s++) {
        if (s < nIter) issue(s, s);
        cp_commit();
    }

    for (int it = 0; it < nIter; it++) {
        cp_wait<HSTAGE-2>();
        __syncthreads();
        int nx = it + HSTAGE - 1;
        if (nx < nIter) issue(nx, nx & (HSTAGE-1));
        cp_commit();

        int buf = it & (HSTAGE-1);
        uint32_t aB = aBase + buf*(HSTG*2);
        uint32_t bB = bBase + buf*(HSTG*2);

        #pragma unroll
        for (int kk = 0; kk < 2; kk++) {
            uint32_t af[4][4], bf[4][2];
            #pragma unroll
            for (int mt = 0; mt < 4; mt++) {
                uint32_t ad = aB + ((aRow + mt*16)*HLD + kk*16 + aCol)*2;
                LDSM_X4(af[mt][0], af[mt][1], af[mt][2], af[mt][3], ad);
            }
            #pragma unroll
            for (int ntp = 0; ntp < 2; ntp++) {
                uint32_t bd = bB + ((bRow + ntp*16)*HLD + kk*16 + bCol)*2;
                LDSM_X4(bf[2*ntp][0], bf[2*ntp][1], bf[2*ntp+1][0], bf[2*ntp+1][1], bd);
            }
            #pragma unroll
            for (int mt = 0; mt < 4; mt++)
                #pragma unroll
                for (int nt = 0; nt < 4; nt++)
                    MMA_F16(acc[mt][nt][0], acc[mt][nt][1], acc[mt][nt][2], acc[mt][nt][3],
                            af[mt][0], af[mt][1], af[mt][2], af[mt][3],
                            bf[nt][0], bf[nt][1]);
        }
    }

    // epilogue: pair (q0,q1)/(q2,q3) -> column-adjacent vector stores
    #pragma unroll
    for (int mt = 0; mt < 4; mt++) {
        #pragma unroll
        for (int nt = 0; nt < 4; nt++) {
            #pragma unroll
            for (int half = 0; half < 2; half++) {
                int gm = m0 + wr*64 + mt*16 + (lane >> 2) + half*8;
                int gn = n0 + wc*32 + nt*8 + 2*(lane & 3);
                float v0 = acc[mt][nt][half*2 + 0];
                float v1 = acc[mt][nt][half*2 + 1];
                if (EPI == EPI_PART) {
                    if (gn < N) {
                        float* dst = (float*)Cv + (size_t)blockIdx.z*TOK*PC + (size_t)gm*ldc + gn;
                        dst[0] = v0;
                        if (gn + 1 < N) dst[1] = v1;
                    }
                    continue;
                }
                v0 += bias[gn]; v1 += bias[gn+1];
                if (EPI == EPI_SPLIT_SILU) {
                    float s0 = v0 / (1.f + __expf(-v0));
                    float s1 = v1 / (1.f + __expf(-v1));
                    __half2 hv = __floats2half2_rn(s0, s1);
                    if (gn < Eq) *(__half2*)((__half*)Cv + (size_t)gm*Eq + gn) = hv;
                    else         *(__half2*)(gate + (size_t)gm*Eq + gn - Eq)  = hv;
                } else if (EPI == EPI_SOFTPLUS) {
                    float s0 = (v0 > 20.f) ? v0 : log1pf(__expf(v0));
                    float s1 = (v1 > 20.f) ? v1 : log1pf(__expf(v1));
                    *(__half2*)((__half*)Cv + (size_t)gm*ldc + gn) = __floats2half2_rn(s0, s1);
                } else { // EPI_RES
                    const float2 r2 = *(const float2*)(resid + (size_t)gm*ldc + gn);
                    float2 f2; f2.x = v0 + r2.x; f2.y = v1 + r2.y;
                    *(float2*)((float*)Cv + (size_t)gm*ldc + gn) = f2;
                }
            }
        }
    }
}

// ---------------- chunked selective scan (f16x2 exp path) ----------------
#define LOG2E 1.4426950408889634f

__global__ void __launch_bounds__(256)
scan_p1(const float* __restrict__ A_log) {
    int gw    = blockIdx.x*8 + (threadIdx.x >> 5);
    int lane  = threadIdx.x & 31;
    int egrp  = gw & 127;
    int chunk = gw >> 7;
    int c = egrp*32 + lane;
    int b = c >> 11;
    int e = c & (Eq-1);
    int t0 = chunk * CT;

    __half2 Aen2[8];
    #pragma unroll
    for (int p = 0; p < 8; p++) {
        float a0 = -__expf(A_log[e*Nq + 2*p    ]) * LOG2E;
        float a1 = -__expf(A_log[e*Nq + 2*p + 1]) * LOG2E;
        Aen2[p] = __floats2half2_rn(a0, a1);
    }

    float h[Nq], ap[Nq];
    #pragma unroll
    for (int n = 0; n < Nq; n++) { h[n] = 0.f; ap[n] = 1.f; }

    const __half* dp = g_delta + ((size_t)b*Lq + t0)*Eq + e;
    const __half* up = g_u     + ((size_t)b*Lq + t0)*Eq + e;

    #pragma unroll 2
    for (int t = 0; t < CT; t++) {
        __half dh = dp[(size_t)t*Eq];
        float d  = __half2float(dh);
        float xv = __half2float(up[(size_t)t*Eq]);
        float dx = d * xv;
        __half2 dh2 = __half2half2(dh);
        float da[Nq];
        #pragma unroll
        for (int p = 0; p < 8; p++) {
            float2 f = __half22float2(h2exp2(__hmul2(dh2, Aen2[p])));
            da[2*p] = f.x; da[2*p+1] = f.y;
        }
        const float4* pB4 = (const float4*)(g_P + ((size_t)b*Lq + t0 + t)*PC + 64);
        #pragma unroll
        for (int q = 0; q < 4; q++) {
            float4 Bv = __ldg(pB4 + q);
            float bb[4] = {Bv.x, Bv.y, Bv.z, Bv.w};
            #pragma unroll
            for (int r = 0; r < 4; r++) {
                int n = q*4 + r;
                ap[n] *= da[n];
                h[n] = fmaf(da[n], h[n], dx * bb[r]);
            }
        }
    }
    float4* apo = (float4*)(g_ap + ((size_t)chunk*NCHAN + c)*Nq);
    float4* co  = (float4*)(g_c  + ((size_t)chunk*NCHAN + c)*Nq);
    #pragma unroll
    for (int q = 0; q < 4; q++) {
        apo[q] = make_float4(ap[q*4], ap[q*4+1], ap[q*4+2], ap[q*4+3]);
        co[q]  = make_float4(h[q*4],  h[q*4+1],  h[q*4+2],  h[q*4+3]);
    }
}

__global__ void __launch_bounds__(256)
scan_p2() {
    int i = blockIdx.x*blockDim.x + threadIdx.x;
    if (i >= NCHAN*Nq) return;
    float hin = 0.f;
    #pragma unroll
    for (int k = 0; k < NCHUNK; k++) {
        size_t idx = (size_t)k*NCHAN*Nq + i;
        g_hin[idx] = hin;
        hin = g_ap[idx]*hin + g_c[idx];
    }
}

__global__ void __launch_bounds__(256)
scan_p3(const float* __restrict__ A_log, const float* __restrict__ Dv) {
    int gw    = blockIdx.x*8 + (threadIdx.x >> 5);
    int lane  = threadIdx.x & 31;
    int egrp  = gw & 127;
    int chunk = gw >> 7;
    int c = egrp*32 + lane;
    int b = c >> 11;
    int e = c & (Eq-1);
    int t0 = chunk * CT;

    __half2 Aen2[8];
    #pragma unroll
    for (int p = 0; p < 8; p++) {
        float a0 = -__expf(A_log[e*Nq + 2*p    ]) * LOG2E;
        float a1 = -__expf(A_log[e*Nq + 2*p + 1]) * LOG2E;
        Aen2[p] = __floats2half2_rn(a0, a1);
    }
    float De = Dv[e];

    float h[Nq];
    const float4* hi = (const float4*)(g_hin + ((size_t)chunk*NCHAN + c)*Nq);
    #pragma unroll
    for (int q = 0; q < 4; q++) {
        float4 v = hi[q];
        h[q*4] = v.x; h[q*4+1] = v.y; h[q*4+2] = v.z; h[q*4+3] = v.w;
    }

    const __half* dp = g_delta + ((size_t)b*Lq + t0)*Eq + e;
    const __half* up = g_u     + ((size_t)b*Lq + t0)*Eq + e;
    const __half* gp = g_gate  + ((size_t)b*Lq + t0)*Eq + e;
    __half*       yp = g_y     + ((size_t)b*Lq + t0)*Eq + e;

    #pragma unroll 2
    for (int t = 0; t < CT; t++) {
        __half dh = dp[(size_t)t*Eq];
        float d  = __half2float(dh);
        float xv = __half2float(up[(size_t)t*Eq]);
        float dx = d * xv;
        __half2 dh2 = __half2half2(dh);
        float da[Nq];
        #pragma unroll
        for (int p = 0; p < 8; p++) {
            float2 f = __half22float2(h2exp2(__hmul2(dh2, Aen2[p])));
            da[2*p] = f.x; da[2*p+1] = f.y;
        }
        const float4* pB4 = (const float4*)(g_P + ((size_t)b*Lq + t0 + t)*PC + 64);
        float y = 0.f;
        #pragma unroll
        for (int q = 0; q < 4; q++) {
            float4 Bv = __ldg(pB4 + q);
            float4 Cvv = __ldg(pB4 + 4 + q);
            float bb[4] = {Bv.x, Bv.y, Bv.z, Bv.w};
            float cc[4] = {Cvv.x, Cvv.y, Cvv.z, Cvv.w};
            #pragma unroll
            for (int r = 0; r < 4; r++) {
                int n = q*4 + r;
                h[n] = fmaf(da[n], h[n], dx * bb[r]);
                y = fmaf(cc[r], h[n], y);
            }
        }
        float g = __half2float(gp[(size_t)t*Eq]);
        yp[(size_t)t*Eq] = __float2half_rn(fmaf(xv, De, y) * g);
    }
}

// ---------------- launch ----------------
extern "C" void kernel_launch(void* const* d_in, const int* in_sizes, int n_in,
                              void* d_out, int out_size) {
    const float* x       = (const float*)d_in[0];
    const float* lng     = (const float*)d_in[1];
    const float* lnb     = (const float*)d_in[2];
    const float* W_in    = (const float*)d_in[3];
    const float* b_in    = (const float*)d_in[4];
    const float* W_delta = (const float*)d_in[5];
    const float* b_delta = (const float*)d_in[6];
    const float* W_dt    = (const float*)d_in[7];
    const float* b_dt    = (const float*)d_in[8];
    const float* W_B     = (const float*)d_in[9];
    const float* b_B     = (const float*)d_in[10];
    const float* W_C     = (const float*)d_in[11];
    const float* b_C     = (const float*)d_in[12];
    const float* A_log   = (const float*)d_in[13];
    const float* Dv      = (const float*)d_in[14];
    const float* W_out   = (const float*)d_in[15];
    const float* b_out   = (const float*)d_in[16];
    float* out = (float*)d_out;

    void *p_xn, *p_u, *p_gate, *p_Ph, *p_Ppart, *p_delta, *p_y;
    void *p_WcatT, *p_WtIn, *p_WtDt, *p_WtOut;
    cudaGetSymbolAddress(&p_xn,    g_xn);
    cudaGetSymbolAddress(&p_u,     g_u);
    cudaGetSymbolAddress(&p_gate,  g_gate);
    cudaGetSymbolAddress(&p_Ph,    g_Ph);
    cudaGetSymbolAddress(&p_Ppart, g_Ppart);
    cudaGetSymbolAddress(&p_delta, g_delta);
    cudaGetSymbolAddress(&p_y,     g_y);
    cudaGetSymbolAddress(&p_WcatT, g_WcatT);
    cudaGetSymbolAddress(&p_WtIn,  g_WtIn);
    cudaGetSymbolAddress(&p_WtDt,  g_WtDt);
    cudaGetSymbolAddress(&p_WtOut, g_WtOut);

    static bool attr_done = false;
    if (!attr_done) {
        cudaFuncSetAttribute(gemm_h<EPI_SPLIT_SILU>, cudaFuncAttributeMaxDynamicSharedMemorySize, H_SMEM);
        cudaFuncSetAttribute(gemm_h<EPI_SOFTPLUS>,   cudaFuncAttributeMaxDynamicSharedMemorySize, H_SMEM);
        cudaFuncSetAttribute(gemm_h<EPI_RES>,        cudaFuncAttributeMaxDynamicSharedMemorySize, H_SMEM);
        cudaFuncSetAttribute(gemm_h<EPI_PART>,       cudaFuncAttributeMaxDynamicSharedMemorySize, H_SMEM);
        attr_done = true;
    }

    // prep (fused): fp16 transposed weights + packed proj weight
    prep_kernel<<<PREP_BLOCKS, 256>>>(W_in, W_out, W_dt,
                                      W_delta, W_B, W_C, b_delta, b_B, b_C);
    // LayerNorm -> fp16 xn
    ln_kernel<<<TOK, 256>>>(x, lng, lnb);
    // GEMM1: xn @ W_in -> silu(u), silu(gate)
    gemm_h<EPI_SPLIT_SILU><<<dim3(2*Eq/128, TOK/128), 256, H_SMEM>>>(
        (const __half*)p_xn, Hq, (const __half*)p_WtIn, Hq, b_in,
        p_u, Eq, nullptr, (__half*)p_gate, TOK, 2*Eq, Hq, Hq);
    // P partials = u @ Wcat (split-K), reduce (+fp16 copy of delta part)
    gemm_h<EPI_PART><<<dim3(1, TOK/128, KSPLIT), 256, H_SMEM>>>(
        (const __half*)p_u, Eq, (const __half*)p_WcatT, Eq, nullptr,
        p_Ppart, PC, nullptr, nullptr, TOK, PC, Eq, Eq/KSPLIT);
    reduceP_kernel<<<(TOK*PC + 255)/256, 256>>>();
    // delta = softplus(Ph @ W_dt) -> fp16
    gemm_h<EPI_SOFTPLUS><<<dim3(Eq/128, TOK/128), 256, H_SMEM>>>(
        (const __half*)p_Ph, 64, (const __half*)p_WtDt, Rq, b_dt,
        p_delta, Eq, nullptr, nullptr, TOK, Eq, Rq, Rq);
    // chunked selective scan
    scan_p1<<<(NCHAN/32)*NCHUNK/8, 256>>>(A_log);
    scan_p2<<<(NCHAN*Nq + 255)/256, 256>>>();
    scan_p3<<<(NCHAN/32)*NCHUNK/8, 256>>>(A_log, Dv);
    // out = y @ W_out + b_out + residual
    gemm_h<EPI_RES><<<dim3(Hq/128, TOK/128), 256, H_SMEM>>>(
        (const __half*)p_y, Eq, (const __half*)p_WtOut, Eq, b_out,
        out, Hq, x, nullptr, TOK, Hq, Eq, Eq);
}

// round 14
// speedup vs baseline: 1.1433x; 1.0474x over previous
#include <cuda_runtime.h>
#include <cuda_fp16.h>
#include <math.h>
#include <stdint.h>

// Problem constants
#define Bq   2
#define Lq   2048
#define Hq   1024
#define Eq   2048
#define Nq   16
#define Rq   64
#define TOK  (Bq*Lq)        // 4096 tokens
#define PC   96             // packed proj cols: 64 (delta) + 16 (B) + 16 (C)
#define PCP  128            // padded N for P-GEMM
#define KSPLIT 8
#define NCHUNK 32           // scan chunks
#define CT    (Lq/NCHUNK)   // 64 timesteps per chunk
#define NCHAN (Bq*Eq)       // 4096 channels

// ---------------- device scratch (allocation-free) ----------------
__device__ __align__(16) __half g_xn[TOK*Hq];      // layernormed input (fp16)
__device__ __align__(16) __half g_u[TOK*Eq];       // silu(u) fp16
__device__ __align__(16) __half g_gate[TOK*Eq];    // silu(gate) fp16
__device__ __align__(16) __half g_y[TOK*Eq];       // scan output fp16
__device__ __align__(16) float  g_P[TOK*PC];       // [delta_proj(64) | B(16) | C(16)] f32
__device__ __align__(16) __half g_Ph[TOK*64];      // delta-proj part, fp16 (GEMM input)
__device__ __align__(16) float  g_Ppart[KSPLIT*TOK*PC];
__device__ __align__(16) __half g_delta[TOK*Eq];   // softplus delta fp16
__device__ __align__(16) __half g_WcatT[PCP*Eq];   // [delta|B|C]^T padded, fp16
__device__ float g_bcat[PC];
__device__ __align__(16) __half g_WtIn[2*Eq*Hq];   // W_in^T  [4096][1024] fp16
__device__ __align__(16) __half g_WtDt[Eq*Rq];     // W_dt^T  [2048][64]   fp16
__device__ __align__(16) __half g_WtOut[Hq*Eq];    // W_out^T [1024][2048] fp16
// chunked-scan state: [chunk][chan][n]
__device__ __align__(16) float g_ap [NCHUNK*NCHAN*Nq];
__device__ __align__(16) float g_c  [NCHUNK*NCHAN*Nq];
__device__ __align__(16) float g_hin[NCHUNK*NCHAN*Nq];

__device__ __forceinline__ uint32_t sptr(const void* p) {
    return (uint32_t)__cvta_generic_to_shared(p);
}

// ---------------- LayerNorm (writes fp16 xn) ----------------
__global__ void ln_kernel(const float* __restrict__ x,
                          const float* __restrict__ gamma,
                          const float* __restrict__ beta) {
    int m = blockIdx.x;
    const float* row = x + (size_t)m*Hq;
    float s = 0.f, s2 = 0.f;
    for (int i = threadIdx.x; i < Hq; i += blockDim.x) {
        float v = row[i]; s += v; s2 += v*v;
    }
    __shared__ float sh[64];
    for (int o = 16; o; o >>= 1) {
        s  += __shfl_xor_sync(~0u, s,  o);
        s2 += __shfl_xor_sync(~0u, s2, o);
    }
    int wid = threadIdx.x >> 5, lane = threadIdx.x & 31;
    if (lane == 0) { sh[wid] = s; sh[32+wid] = s2; }
    __syncthreads();
    if (wid == 0) {
        int nw = blockDim.x >> 5;
        s  = (lane < nw) ? sh[lane]    : 0.f;
        s2 = (lane < nw) ? sh[32+lane] : 0.f;
        for (int o = 16; o; o >>= 1) {
            s  += __shfl_xor_sync(~0u, s,  o);
            s2 += __shfl_xor_sync(~0u, s2, o);
        }
        if (lane == 0) { sh[0] = s; sh[1] = s2; }
    }
    __syncthreads();
    float mu  = sh[0] * (1.f/Hq);
    float var = sh[1] * (1.f/Hq) - mu*mu;
    float inv = rsqrtf(var + 1e-5f);
    for (int i = threadIdx.x; i < Hq; i += blockDim.x) {
        g_xn[(size_t)m*Hq + i] = __float2half_rn((row[i]-mu)*inv*gamma[i] + beta[i]);
    }
}

// ---------------- fused prep: 3 transposes + pack, one launch ----------------
#define PREP_BLOCKS 7296
__global__ void prep_kernel(const float* __restrict__ W_in,
                            const float* __restrict__ W_out,
                            const float* __restrict__ W_dt,
                            const float* __restrict__ Wd, const float* __restrict__ Wb,
                            const float* __restrict__ Wc, const float* __restrict__ bd,
                            const float* __restrict__ bb, const float* __restrict__ bc) {
    int blk = blockIdx.x;
    if (blk < 6272) {
        const float* src; __half* dst; int R, Cc, bx, nbx;
        if (blk < 4096)      { src = W_in;  dst = g_WtIn;  R = Hq; Cc = 2*Eq; bx = blk;        nbx = 2*Eq/32; }
        else if (blk < 6144) { src = W_out; dst = g_WtOut; R = Eq; Cc = Hq;   bx = blk - 4096; nbx = Hq/32; }
        else                 { src = W_dt;  dst = g_WtDt;  R = Rq; Cc = Eq;   bx = blk - 6144; nbx = Eq/32; }
        int c0 = (bx % nbx) * 32, r0 = (bx / nbx) * 32;
        int tx = threadIdx.x & 31, ty = threadIdx.x >> 5;
        __shared__ float t[32][33];
        for (int i = ty; i < 32; i += 8)
            t[i][tx] = src[(size_t)(r0+i)*Cc + c0 + tx];
        __syncthreads();
        for (int i = ty; i < 32; i += 8)
            dst[(size_t)(c0+i)*R + r0 + tx] = __float2half_rn(t[tx][i]);
    } else {
        int i = (blk - 6272)*256 + threadIdx.x;
        if (i < PCP*Eq) {
            int c = i / Eq, k = i % Eq;
            float v = 0.f;
            if (c < 64)      v = Wd[k*64 + c];
            else if (c < 80) v = Wb[k*16 + (c-64)];
            else if (c < 96) v = Wc[k*16 + (c-80)];
            g_WcatT[i] = __float2half_rn(v);
        }
        if (i < PC) {
            g_bcat[i] = (i < 64) ? bd[i] : ((i < 80) ? bb[i-64] : bc[i-80]);
        }
    }
}

// ---------------- split-K reduction for P (f32 + fp16 delta part) -----------
__global__ void reduceP_kernel() {
    int i = blockIdx.x*blockDim.x + threadIdx.x;
    if (i >= TOK*PC) return;
    int c = i % PC, m = i / PC;
    float s = g_bcat[c];
    #pragma unroll
    for (int z = 0; z < KSPLIT; z++) s += g_Ppart[(size_t)z*TOK*PC + i];
    g_P[i] = s;
    if (c < 64) g_Ph[(size_t)m*64 + c] = __float2half_rn(s);
}

// ======== fp16 m16n8k16 GEMM, 8 warps, BK=64, 3-stage cp.async ==============
enum { EPI_SPLIT_SILU = 1, EPI_SOFTPLUS = 2, EPI_RES = 3, EPI_PART = 4 };

#define MMA_F16(c0,c1,c2,c3,a0,a1,a2,a3,b0,b1) \
    asm volatile("mma.sync.aligned.m16n8k16.row.col.f32.f16.f16.f32 " \
                 "{%0,%1,%2,%3},{%4,%5,%6,%7},{%8,%9},{%0,%1,%2,%3};" \
                 : "+f"(c0),"+f"(c1),"+f"(c2),"+f"(c3) \
                 : "r"(a0),"r"(a1),"r"(a2),"r"(a3),"r"(b0),"r"(b1))

#define LDSM_X4(r0,r1,r2,r3,addr) \
    asm volatile("ldmatrix.sync.aligned.m8n8.x4.shared.b16 {%0,%1,%2,%3}, [%4];" \
                 : "=r"(r0),"=r"(r1),"=r"(r2),"=r"(r3) : "r"(addr))

template<int N> __device__ __forceinline__ void cp_wait() {
    asm volatile("cp.async.wait_group %0;" :: "n"(N));
}
__device__ __forceinline__ void cp_commit() {
    asm volatile("cp.async.commit_group;" ::);
}

#define HBM 128
#define HBN 128
#define HBK 64
#define HSTAGE 3
#define HLD 72                      // halves per row (64 + 8 pad) = 144 bytes
#define HSTG (HBM*HLD)              // halves per stage tile (9216)
#define H_SMEM (HSTAGE*HSTG*2*2)    // A + B regions, bytes (110592)

template<int EPI>
__global__ void __launch_bounds__(256, 2)
gemm_h(const __half* __restrict__ A, int lda,
       const __half* __restrict__ Bt, int ldb,    // [N][K] K-major
       const float* __restrict__ bias,
       void* __restrict__ Cv, int ldc,
       const float* __restrict__ resid,           // residual (RES)
       __half* __restrict__ gate,                 // gate out (SPLIT_SILU)
       int M, int N, int K, int Kchunk)
{
    extern __shared__ __half smh[];
    __half* Asm = smh;
    __half* Bsm = smh + HSTAGE*HSTG;
    const uint32_t aBase = sptr(Asm);
    const uint32_t bBase = sptr(Bsm);

    const int tid  = threadIdx.x;
    const int lane = tid & 31;
    const int warp = tid >> 5;
    const int wr   = warp & 1;          // 2 x 64 rows
    const int wc   = warp >> 1;         // 4 x 32 cols
    const int m0   = blockIdx.y * HBM;
    const int n0   = blockIdx.x * HBN;
    const int Koff = blockIdx.z * Kchunk;

    const uint32_t aRow = wr*64 + (lane & 15);
    const uint32_t aCol = (lane >> 4) * 8;
    const uint32_t bRow = wc*32 + (lane & 7) + ((lane >> 4) << 3);
    const uint32_t bCol = ((lane >> 3) & 1) * 8;

    auto issue = [&](int it, int buf) {
        int k0 = Koff + it * HBK;
        #pragma unroll
        for (int j = 0; j < 4; j++) {
            int id = tid + j*256;
            int row = id >> 3, slot = id & 7;
            const __half* as = A  + (size_t)(m0 + row)*lda + k0 + slot*8;
            const __half* bs = Bt + (size_t)(n0 + row)*ldb + k0 + slot*8;
            asm volatile("cp.async.ca.shared.global [%0], [%1], 16;\n"
                         :: "r"(aBase + buf*(HSTG*2) + row*144 + slot*16), "l"(as));
            asm volatile("cp.async.ca.shared.global [%0], [%1], 16;\n"
                         :: "r"(bBase + buf*(HSTG*2) + row*144 + slot*16), "l"(bs));
        }
    };

    float acc[4][4][4];
    #pragma unroll
    for (int i = 0; i < 4; i++)
        #pragma unroll
        for (int j = 0; j < 4; j++)
            #pragma unroll
            for (int k = 0; k < 4; k++) acc[i][j][k] = 0.f;

    const int nIter = Kchunk / HBK;
    #pragma unroll
    for (int s = 0; s < HSTAGE-1; s++) {
        if (s < nIter) issue(s, s);
        cp_commit();
    }

    for (int it = 0; it < nIter; it++) {
        cp_wait<HSTAGE-2>();
        __syncthreads();
        int nx = it + HSTAGE - 1;
        if (nx < nIter) issue(nx, nx % HSTAGE);
        cp_commit();

        int buf = it % HSTAGE;
        uint32_t aB = aBase + buf*(HSTG*2);
        uint32_t bB = bBase + buf*(HSTG*2);

        #pragma unroll
        for (int kk = 0; kk < 4; kk++) {
            uint32_t af[4][4], bf[4][2];
            #pragma unroll
            for (int mt = 0; mt < 4; mt++) {
                uint32_t ad = aB + ((aRow + mt*16)*HLD + kk*16 + aCol)*2;
                LDSM_X4(af[mt][0], af[mt][1], af[mt][2], af[mt][3], ad);
            }
            #pragma unroll
            for (int ntp = 0; ntp < 2; ntp++) {
                uint32_t bd = bB + ((bRow + ntp*16)*HLD + kk*16 + bCol)*2;
                LDSM_X4(bf[2*ntp][0], bf[2*ntp][1], bf[2*ntp+1][0], bf[2*ntp+1][1], bd);
            }
            #pragma unroll
            for (int mt = 0; mt < 4; mt++)
                #pragma unroll
                for (int nt = 0; nt < 4; nt++)
                    MMA_F16(acc[mt][nt][0], acc[mt][nt][1], acc[mt][nt][2], acc[mt][nt][3],
                            af[mt][0], af[mt][1], af[mt][2], af[mt][3],
                            bf[nt][0], bf[nt][1]);
        }
    }

    // epilogue: pair (q0,q1)/(q2,q3) -> column-adjacent vector stores
    #pragma unroll
    for (int mt = 0; mt < 4; mt++) {
        #pragma unroll
        for (int nt = 0; nt < 4; nt++) {
            #pragma unroll
            for (int half = 0; half < 2; half++) {
                int gm = m0 + wr*64 + mt*16 + (lane >> 2) + half*8;
                int gn = n0 + wc*32 + nt*8 + 2*(lane & 3);
                float v0 = acc[mt][nt][half*2 + 0];
                float v1 = acc[mt][nt][half*2 + 1];
                if (EPI == EPI_PART) {
                    if (gn < N) {
                        float* dst = (float*)Cv + (size_t)blockIdx.z*TOK*PC + (size_t)gm*ldc + gn;
                        dst[0] = v0;
                        if (gn + 1 < N) dst[1] = v1;
                    }
                    continue;
                }
                v0 += bias[gn]; v1 += bias[gn+1];
                if (EPI == EPI_SPLIT_SILU) {
                    float s0 = v0 / (1.f + __expf(-v0));
                    float s1 = v1 / (1.f + __expf(-v1));
                    __half2 hv = __floats2half2_rn(s0, s1);
                    if (gn < Eq) *(__half2*)((__half*)Cv + (size_t)gm*Eq + gn) = hv;
                    else         *(__half2*)(gate + (size_t)gm*Eq + gn - Eq)  = hv;
                } else if (EPI == EPI_SOFTPLUS) {
                    float s0 = (v0 > 20.f) ? v0 : log1pf(__expf(v0));
                    float s1 = (v1 > 20.f) ? v1 : log1pf(__expf(v1));
                    *(__half2*)((__half*)Cv + (size_t)gm*ldc + gn) = __floats2half2_rn(s0, s1);
                } else { // EPI_RES
                    const float2 r2 = *(const float2*)(resid + (size_t)gm*ldc + gn);
                    float2 f2; f2.x = v0 + r2.x; f2.y = v1 + r2.y;
                    *(float2*)((float*)Cv + (size_t)gm*ldc + gn) = f2;
                }
            }
        }
    }
}

// ---------------- chunked selective scan (f16x2 exp path) ----------------
#define LOG2E 1.4426950408889634f

__global__ void __launch_bounds__(256)
scan_p1(const float* __restrict__ A_log) {
    int gw    = blockIdx.x*8 + (threadIdx.x >> 5);
    int lane  = threadIdx.x & 31;
    int egrp  = gw & 127;
    int chunk = gw >> 7;
    int c = egrp*32 + lane;
    int b = c >> 11;
    int e = c & (Eq-1);
    int t0 = chunk * CT;

    __half2 Aen2[8];
    #pragma unroll
    for (int p = 0; p < 8; p++) {
        float a0 = -__expf(A_log[e*Nq + 2*p    ]) * LOG2E;
        float a1 = -__expf(A_log[e*Nq + 2*p + 1]) * LOG2E;
        Aen2[p] = __floats2half2_rn(a0, a1);
    }

    float h[Nq], ap[Nq];
    #pragma unroll
    for (int n = 0; n < Nq; n++) { h[n] = 0.f; ap[n] = 1.f; }

    const __half* dp = g_delta + ((size_t)b*Lq + t0)*Eq + e;
    const __half* up = g_u     + ((size_t)b*Lq + t0)*Eq + e;

    #pragma unroll 2
    for (int t = 0; t < CT; t++) {
        __half dh = dp[(size_t)t*Eq];
        float d  = __half2float(dh);
        float xv = __half2float(up[(size_t)t*Eq]);
        float dx = d * xv;
        __half2 dh2 = __half2half2(dh);
        float da[Nq];
        #pragma unroll
        for (int p = 0; p < 8; p++) {
            float2 f = __half22float2(h2exp2(__hmul2(dh2, Aen2[p])));
            da[2*p] = f.x; da[2*p+1] = f.y;
        }
        const float4* pB4 = (const float4*)(g_P + ((size_t)b*Lq + t0 + t)*PC + 64);
        #pragma unroll
        for (int q = 0; q < 4; q++) {
            float4 Bv = __ldg(pB4 + q);
            float bb[4] = {Bv.x, Bv.y, Bv.z, Bv.w};
            #pragma unroll
            for (int r = 0; r < 4; r++) {
                int n = q*4 + r;
                ap[n] *= da[n];
                h[n] = fmaf(da[n], h[n], dx * bb[r]);
            }
        }
    }
    float4* apo = (float4*)(g_ap + ((size_t)chunk*NCHAN + c)*Nq);
    float4* co  = (float4*)(g_c  + ((size_t)chunk*NCHAN + c)*Nq);
    #pragma unroll
    for (int q = 0; q < 4; q++) {
        apo[q] = make_float4(ap[q*4], ap[q*4+1], ap[q*4+2], ap[q*4+3]);
        co[q]  = make_float4(h[q*4],  h[q*4+1],  h[q*4+2],  h[q*4+3]);
    }
}

__global__ void __launch_bounds__(256)
scan_p2() {
    int i = blockIdx.x*blockDim.x + threadIdx.x;
    if (i >= NCHAN*Nq) return;
    float hin = 0.f;
    #pragma unroll
    for (int k = 0; k < NCHUNK; k++) {
        size_t idx = (size_t)k*NCHAN*Nq + i;
        g_hin[idx] = hin;
        hin = g_ap[idx]*hin + g_c[idx];
    }
}

__global__ void __launch_bounds__(256)
scan_p3(const float* __restrict__ A_log, const float* __restrict__ Dv) {
    int gw    = blockIdx.x*8 + (threadIdx.x >> 5);
    int lane  = threadIdx.x & 31;
    int egrp  = gw & 127;
    int chunk = gw >> 7;
    int c = egrp*32 + lane;
    int b = c >> 11;
    int e = c & (Eq-1);
    int t0 = chunk * CT;

    __half2 Aen2[8];
    #pragma unroll
    for (int p = 0; p < 8; p++) {
        float a0 = -__expf(A_log[e*Nq + 2*p    ]) * LOG2E;
        float a1 = -__expf(A_log[e*Nq + 2*p + 1]) * LOG2E;
        Aen2[p] = __floats2half2_rn(a0, a1);
    }
    float De = Dv[e];

    float h[Nq];
    const float4* hi = (const float4*)(g_hin + ((size_t)chunk*NCHAN + c)*Nq);
    #pragma unroll
    for (int q = 0; q < 4; q++) {
        float4 v = hi[q];
        h[q*4] = v.x; h[q*4+1] = v.y; h[q*4+2] = v.z; h[q*4+3] = v.w;
    }

    const __half* dp = g_delta + ((size_t)b*Lq + t0)*Eq + e;
    const __half* up = g_u     + ((size_t)b*Lq + t0)*Eq + e;
    const __half* gp = g_gate  + ((size_t)b*Lq + t0)*Eq + e;
    __half*       yp = g_y     + ((size_t)b*Lq + t0)*Eq + e;

    #pragma unroll 2
    for (int t = 0; t < CT; t++) {
        __half dh = dp[(size_t)t*Eq];
        float d  = __half2float(dh);
        float xv = __half2float(up[(size_t)t*Eq]);
        float dx = d * xv;
        __half2 dh2 = __half2half2(dh);
        float da[Nq];
        #pragma unroll
        for (int p = 0; p < 8; p++) {
            float2 f = __half22float2(h2exp2(__hmul2(dh2, Aen2[p])));
            da[2*p] = f.x; da[2*p+1] = f.y;
        }
        const float4* pB4 = (const float4*)(g_P + ((size_t)b*Lq + t0 + t)*PC + 64);
        float y = 0.f;
        #pragma unroll
        for (int q = 0; q < 4; q++) {
            float4 Bv = __ldg(pB4 + q);
            float4 Cvv = __ldg(pB4 + 4 + q);
            float bb[4] = {Bv.x, Bv.y, Bv.z, Bv.w};
            float cc[4] = {Cvv.x, Cvv.y, Cvv.z, Cvv.w};
            #pragma unroll
            for (int r = 0; r < 4; r++) {
                int n = q*4 + r;
                h[n] = fmaf(da[n], h[n], dx * bb[r]);
                y = fmaf(cc[r], h[n], y);
            }
        }
        float g = __half2float(gp[(size_t)t*Eq]);
        yp[(size_t)t*Eq] = __float2half_rn(fmaf(xv, De, y) * g);
    }
}

// ---------------- launch ----------------
extern "C" void kernel_launch(void* const* d_in, const int* in_sizes, int n_in,
                              void* d_out, int out_size) {
    const float* x       = (const float*)d_in[0];
    const float* lng     = (const float*)d_in[1];
    const float* lnb     = (const float*)d_in[2];
    const float* W_in    = (const float*)d_in[3];
    const float* b_in    = (const float*)d_in[4];
    const float* W_delta = (const float*)d_in[5];
    const float* b_delta = (const float*)d_in[6];
    const float* W_dt    = (const float*)d_in[7];
    const float* b_dt    = (const float*)d_in[8];
    const float* W_B     = (const float*)d_in[9];
    const float* b_B     = (const float*)d_in[10];
    const float* W_C     = (const float*)d_in[11];
    const float* b_C     = (const float*)d_in[12];
    const float* A_log   = (const float*)d_in[13];
    const float* Dv      = (const float*)d_in[14];
    const float* W_out   = (const float*)d_in[15];
    const float* b_out   = (const float*)d_in[16];
    float* out = (float*)d_out;

    void *p_xn, *p_u, *p_gate, *p_Ph, *p_Ppart, *p_delta, *p_y;
    void *p_WcatT, *p_WtIn, *p_WtDt, *p_WtOut;
    cudaGetSymbolAddress(&p_xn,    g_xn);
    cudaGetSymbolAddress(&p_u,     g_u);
    cudaGetSymbolAddress(&p_gate,  g_gate);
    cudaGetSymbolAddress(&p_Ph,    g_Ph);
    cudaGetSymbolAddress(&p_Ppart, g_Ppart);
    cudaGetSymbolAddress(&p_delta, g_delta);
    cudaGetSymbolAddress(&p_y,     g_y);
    cudaGetSymbolAddress(&p_WcatT, g_WcatT);
    cudaGetSymbolAddress(&p_WtIn,  g_WtIn);
    cudaGetSymbolAddress(&p_WtDt,  g_WtDt);
    cudaGetSymbolAddress(&p_WtOut, g_WtOut);

    static bool init_done = false;
    static cudaStream_t s2;
    static cudaEvent_t evFork, evJoin;
    if (!init_done) {
        cudaFuncSetAttribute(gemm_h<EPI_SPLIT_SILU>, cudaFuncAttributeMaxDynamicSharedMemorySize, H_SMEM);
        cudaFuncSetAttribute(gemm_h<EPI_SOFTPLUS>,   cudaFuncAttributeMaxDynamicSharedMemorySize, H_SMEM);
        cudaFuncSetAttribute(gemm_h<EPI_RES>,        cudaFuncAttributeMaxDynamicSharedMemorySize, H_SMEM);
        cudaFuncSetAttribute(gemm_h<EPI_PART>,       cudaFuncAttributeMaxDynamicSharedMemorySize, H_SMEM);
        cudaStreamCreateWithFlags(&s2, cudaStreamNonBlocking);
        cudaEventCreateWithFlags(&evFork, cudaEventDisableTiming);
        cudaEventCreateWithFlags(&evJoin, cudaEventDisableTiming);
        init_done = true;
    }

    // fork: prep (weights) on side stream, LN on main stream, join before GEMM1
    cudaEventRecord(evFork, 0);
    cudaStreamWaitEvent(s2, evFork, 0);
    prep_kernel<<<PREP_BLOCKS, 256, 0, s2>>>(W_in, W_out, W_dt,
                                             W_delta, W_B, W_C, b_delta, b_B, b_C);
    cudaEventRecord(evJoin, s2);
    ln_kernel<<<TOK, 256>>>(x, lng, lnb);
    cudaStreamWaitEvent(0, evJoin, 0);

    // GEMM1: xn @ W_in -> silu(u), silu(gate)
    gemm_h<EPI_SPLIT_SILU><<<dim3(2*Eq/128, TOK/128), 256, H_SMEM>>>(
        (const __half*)p_xn, Hq, (const __half*)p_WtIn, Hq, b_in,
        p_u, Eq, nullptr, (__half*)p_gate, TOK, 2*Eq, Hq, Hq);
    // P partials = u @ Wcat (split-K), reduce (+fp16 copy of delta part)
    gemm_h<EPI_PART><<<dim3(1, TOK/128, KSPLIT), 256, H_SMEM>>>(
        (const __half*)p_u, Eq, (const __half*)p_WcatT, Eq, nullptr,
        p_Ppart, PC, nullptr, nullptr, TOK, PC, Eq, Eq/KSPLIT);
    reduceP_kernel<<<(TOK*PC + 255)/256, 256>>>();
    // delta = softplus(Ph @ W_dt) -> fp16
    gemm_h<EPI_SOFTPLUS><<<dim3(Eq/128, TOK/128), 256, H_SMEM>>>(
        (const __half*)p_Ph, 64, (const __half*)p_WtDt, Rq, b_dt,
        p_delta, Eq, nullptr, nullptr, TOK, Eq, Rq, Rq);
    // chunked selective scan
    scan_p1<<<(NCHAN/32)*NCHUNK/8, 256>>>(A_log);
    scan_p2<<<(NCHAN*Nq + 255)/256, 256>>>();
    scan_p3<<<(NCHAN/32)*NCHUNK/8, 256>>>(A_log, Dv);
    // out = y @ W_out + b_out + residual
    gemm_h<EPI_RES><<<dim3(Hq/128, TOK/128), 256, H_SMEM>>>(
        (const __half*)p_y, Eq, (const __half*)p_WtOut, Eq, b_out,
        out, Hq, x, nullptr, TOK, Hq, Eq, Eq);
}

// round 15
// speedup vs baseline: 1.1725x; 1.0255x over previous
#include <cuda_runtime.h>
#include <cuda_fp16.h>
#include <math.h>
#include <stdint.h>

// Problem constants
#define Bq   2
#define Lq   2048
#define Hq   1024
#define Eq   2048
#define Nq   16
#define Rq   64
#define TOK  (Bq*Lq)        // 4096 tokens
#define PC   96             // packed proj cols: 64 (delta) + 16 (B) + 16 (C)
#define PCP  128            // padded N for P-GEMM
#define KSPLIT 8
#define NCHUNK 32           // scan chunks
#define CT    (Lq/NCHUNK)   // 64 timesteps per chunk
#define NCHAN (Bq*Eq)       // 4096 channels

// ---------------- device scratch (allocation-free) ----------------
__device__ __align__(16) __half g_xn[TOK*Hq];      // layernormed input (fp16)
__device__ __align__(16) __half g_u[TOK*Eq];       // silu(u) fp16
__device__ __align__(16) __half g_gate[TOK*Eq];    // silu(gate) fp16
__device__ __align__(16) __half g_y[TOK*Eq];       // scan output fp16
__device__ __align__(16) float  g_P[TOK*PC];       // [delta_proj(64) | B(16) | C(16)] f32
__device__ __align__(16) __half g_Ph[TOK*64];      // delta-proj part, fp16 (GEMM input)
__device__ __align__(16) float  g_Ppart[KSPLIT*TOK*PC];
__device__ __align__(16) __half g_delta[TOK*Eq];   // softplus delta fp16
__device__ __align__(16) __half g_WcatT[PCP*Eq];   // [delta|B|C]^T padded, fp16
__device__ float g_bcat[PC];
__device__ __align__(16) __half g_WtIn[2*Eq*Hq];   // W_in^T  [4096][1024] fp16
__device__ __align__(16) __half g_WtDt[Eq*Rq];     // W_dt^T  [2048][64]   fp16
__device__ __align__(16) __half g_WtOut[Hq*Eq];    // W_out^T [1024][2048] fp16
// chunked-scan state: [chunk][chan][n]
__device__ __align__(16) float g_ap [NCHUNK*NCHAN*Nq];
__device__ __align__(16) float g_c  [NCHUNK*NCHAN*Nq];
__device__ __align__(16) float g_hin[NCHUNK*NCHAN*Nq];

__device__ __forceinline__ uint32_t sptr(const void* p) {
    return (uint32_t)__cvta_generic_to_shared(p);
}
__device__ __forceinline__ void mbar_init(uint32_t a, uint32_t cnt) {
    asm volatile("mbarrier.init.shared.b64 [%0], %1;" :: "r"(a), "r"(cnt) : "memory");
}
__device__ __forceinline__ void mbar_expect(uint32_t a, uint32_t bytes) {
    asm volatile("mbarrier.arrive.expect_tx.shared.b64 _, [%0], %1;"
                 :: "r"(a), "r"(bytes) : "memory");
}
__device__ __forceinline__ void mbar_wait(uint32_t a, uint32_t ph) {
    asm volatile("{\n\t.reg .pred P;\n\tWL%=:\n\t"
        "mbarrier.try_wait.parity.acquire.cta.shared::cta.b64 P, [%0], %1, 0x989680;\n\t"
        "@P bra.uni WD%=;\n\tbra.uni WL%=;\n\tWD%=:\n\t}"
        :: "r"(a), "r"(ph) : "memory");
}
__device__ __forceinline__ void bulk_ld(uint32_t dst, const void* src, uint32_t bytes,
                                        uint32_t mbar) {
    asm volatile("cp.async.bulk.shared::cta.global.mbarrier::complete_tx::bytes "
                 "[%0], [%1], %2, [%3];"
                 :: "r"(dst), "l"(src), "r"(bytes), "r"(mbar) : "memory");
}

// ---------------- LayerNorm (writes fp16 xn) ----------------
__global__ void ln_kernel(const float* __restrict__ x,
                          const float* __restrict__ gamma,
                          const float* __restrict__ beta) {
    int m = blockIdx.x;
    const float* row = x + (size_t)m*Hq;
    float s = 0.f, s2 = 0.f;
    for (int i = threadIdx.x; i < Hq; i += blockDim.x) {
        float v = row[i]; s += v; s2 += v*v;
    }
    __shared__ float sh[64];
    for (int o = 16; o; o >>= 1) {
        s  += __shfl_xor_sync(~0u, s,  o);
        s2 += __shfl_xor_sync(~0u, s2, o);
    }
    int wid = threadIdx.x >> 5, lane = threadIdx.x & 31;
    if (lane == 0) { sh[wid] = s; sh[32+wid] = s2; }
    __syncthreads();
    if (wid == 0) {
        int nw = blockDim.x >> 5;
        s  = (lane < nw) ? sh[lane]    : 0.f;
        s2 = (lane < nw) ? sh[32+lane] : 0.f;
        for (int o = 16; o; o >>= 1) {
            s  += __shfl_xor_sync(~0u, s,  o);
            s2 += __shfl_xor_sync(~0u, s2, o);
        }
        if (lane == 0) { sh[0] = s; sh[1] = s2; }
    }
    __syncthreads();
    float mu  = sh[0] * (1.f/Hq);
    float var = sh[1] * (1.f/Hq) - mu*mu;
    float inv = rsqrtf(var + 1e-5f);
    for (int i = threadIdx.x; i < Hq; i += blockDim.x) {
        g_xn[(size_t)m*Hq + i] = __float2half_rn((row[i]-mu)*inv*gamma[i] + beta[i]);
    }
}

// ---------------- fused prep: 3 transposes + pack, one launch ----------------
#define PREP_BLOCKS 7296
__global__ void prep_kernel(const float* __restrict__ W_in,
                            const float* __restrict__ W_out,
                            const float* __restrict__ W_dt,
                            const float* __restrict__ Wd, const float* __restrict__ Wb,
                            const float* __restrict__ Wc, const float* __restrict__ bd,
                            const float* __restrict__ bb, const float* __restrict__ bc) {
    int blk = blockIdx.x;
    if (blk < 6272) {
        const float* src; __half* dst; int R, Cc, bx, nbx;
        if (blk < 4096)      { src = W_in;  dst = g_WtIn;  R = Hq; Cc = 2*Eq; bx = blk;        nbx = 2*Eq/32; }
        else if (blk < 6144) { src = W_out; dst = g_WtOut; R = Eq; Cc = Hq;   bx = blk - 4096; nbx = Hq/32; }
        else                 { src = W_dt;  dst = g_WtDt;  R = Rq; Cc = Eq;   bx = blk - 6144; nbx = Eq/32; }
        int c0 = (bx % nbx) * 32, r0 = (bx / nbx) * 32;
        int tx = threadIdx.x & 31, ty = threadIdx.x >> 5;
        __shared__ float t[32][33];
        for (int i = ty; i < 32; i += 8)
            t[i][tx] = src[(size_t)(r0+i)*Cc + c0 + tx];
        __syncthreads();
        for (int i = ty; i < 32; i += 8)
            dst[(size_t)(c0+i)*R + r0 + tx] = __float2half_rn(t[tx][i]);
    } else {
        int i = (blk - 6272)*256 + threadIdx.x;
        if (i < PCP*Eq) {
            int c = i / Eq, k = i % Eq;
            float v = 0.f;
            if (c < 64)      v = Wd[k*64 + c];
            else if (c < 80) v = Wb[k*16 + (c-64)];
            else if (c < 96) v = Wc[k*16 + (c-80)];
            g_WcatT[i] = __float2half_rn(v);
        }
        if (i < PC) {
            g_bcat[i] = (i < 64) ? bd[i] : ((i < 80) ? bb[i-64] : bc[i-80]);
        }
    }
}

// ---------------- split-K reduction for P (f32 + fp16 delta part) -----------
__global__ void reduceP_kernel() {
    int i = blockIdx.x*blockDim.x + threadIdx.x;
    if (i >= TOK*PC) return;
    int c = i % PC, m = i / PC;
    float s = g_bcat[c];
    #pragma unroll
    for (int z = 0; z < KSPLIT; z++) s += g_Ppart[(size_t)z*TOK*PC + i];
    g_P[i] = s;
    if (c < 64) g_Ph[(size_t)m*64 + c] = __float2half_rn(s);
}

// ======== fp16 m16n8k16 GEMM, 8 warps, BK=64, 3-stage cp.async.bulk =========
enum { EPI_SPLIT_SILU = 1, EPI_SOFTPLUS = 2, EPI_RES = 3, EPI_PART = 4 };

#define MMA_F16(c0,c1,c2,c3,a0,a1,a2,a3,b0,b1) \
    asm volatile("mma.sync.aligned.m16n8k16.row.col.f32.f16.f16.f32 " \
                 "{%0,%1,%2,%3},{%4,%5,%6,%7},{%8,%9},{%0,%1,%2,%3};" \
                 : "+f"(c0),"+f"(c1),"+f"(c2),"+f"(c3) \
                 : "r"(a0),"r"(a1),"r"(a2),"r"(a3),"r"(b0),"r"(b1))

#define LDSM_X4(r0,r1,r2,r3,addr) \
    asm volatile("ldmatrix.sync.aligned.m8n8.x4.shared.b16 {%0,%1,%2,%3}, [%4];" \
                 : "=r"(r0),"=r"(r1),"=r"(r2),"=r"(r3) : "r"(addr))

#define HBM 128
#define HBN 128
#define HBK 64
#define HSTAGE 3
#define HLD 72                      // halves per row (64 + 8 pad) = 144 bytes
#define HSTG (HBM*HLD)              // halves per stage tile (9216)
#define H_TILES (HSTAGE*HSTG*2*2)   // A+B bytes (110592)
#define H_SMEM (H_TILES + 32)       // + mbarriers

template<int EPI>
__global__ void __launch_bounds__(256, 2)
gemm_h(const __half* __restrict__ A, int lda,
       const __half* __restrict__ Bt, int ldb,    // [N][K] K-major
       const float* __restrict__ bias,
       void* __restrict__ Cv, int ldc,
       const float* __restrict__ resid,           // residual (RES)
       __half* __restrict__ gate,                 // gate out (SPLIT_SILU)
       int M, int N, int K, int Kchunk)
{
    extern __shared__ __half smh[];
    const uint32_t aBase = sptr(smh);
    const uint32_t bBase = aBase + HSTAGE*HSTG*2;
    const uint32_t mbar  = aBase + H_TILES;

    const int tid  = threadIdx.x;
    const int lane = tid & 31;
    const int warp = tid >> 5;
    const int wr   = warp & 1;          // 2 x 64 rows
    const int wc   = warp >> 1;         // 4 x 32 cols
    const int m0   = blockIdx.y * HBM;
    const int n0   = blockIdx.x * HBN;
    const int Koff = blockIdx.z * Kchunk;

    const uint32_t aRow = wr*64 + (lane & 15);
    const uint32_t aCol = (lane >> 4) * 8;
    const uint32_t bRow = wc*32 + (lane & 7) + ((lane >> 4) << 3);
    const uint32_t bCol = ((lane >> 3) & 1) * 8;

    if (tid < HSTAGE) mbar_init(mbar + tid*8, 1);
    __syncthreads();

    // per-stage bulk load: one 128B row-copy per thread (128 A rows + 128 B rows)
    const int ldrow = tid & 127;
    auto issue = [&](int it, int buf) {
        int k0 = Koff + it * HBK;
        uint32_t mb = mbar + buf*8;
        if (tid == 0) mbar_expect(mb, 256*128);
        const __half* src = (tid < 128)
            ? (A  + (size_t)(m0 + ldrow)*lda + k0)
            : (Bt + (size_t)(n0 + ldrow)*ldb + k0);
        uint32_t dst = ((tid < 128) ? aBase : bBase) + buf*(HSTG*2) + ldrow*144;
        bulk_ld(dst, src, 128, mb);
    };

    float acc[4][4][4];
    #pragma unroll
    for (int i = 0; i < 4; i++)
        #pragma unroll
        for (int j = 0; j < 4; j++)
            #pragma unroll
            for (int k = 0; k < 4; k++) acc[i][j][k] = 0.f;

    const int nIter = Kchunk / HBK;
    #pragma unroll
    for (int s = 0; s < HSTAGE-1; s++)
        if (s < nIter) issue(s, s);

    for (int it = 0; it < nIter; it++) {
        int buf = it % HSTAGE;
        mbar_wait(mbar + buf*8, (it / HSTAGE) & 1);
        __syncthreads();
        int nx = it + HSTAGE - 1;
        if (nx < nIter) issue(nx, nx % HSTAGE);

        uint32_t aB = aBase + buf*(HSTG*2);
        uint32_t bB = bBase + buf*(HSTG*2);

        #pragma unroll
        for (int kk = 0; kk < 4; kk++) {
            uint32_t af[4][4], bf[4][2];
            #pragma unroll
            for (int mt = 0; mt < 4; mt++) {
                uint32_t ad = aB + ((aRow + mt*16)*HLD + kk*16 + aCol)*2;
                LDSM_X4(af[mt][0], af[mt][1], af[mt][2], af[mt][3], ad);
            }
            #pragma unroll
            for (int ntp = 0; ntp < 2; ntp++) {
                uint32_t bd = bB + ((bRow + ntp*16)*HLD + kk*16 + bCol)*2;
                LDSM_X4(bf[2*ntp][0], bf[2*ntp][1], bf[2*ntp+1][0], bf[2*ntp+1][1], bd);
            }
            #pragma unroll
            for (int mt = 0; mt < 4; mt++)
                #pragma unroll
                for (int nt = 0; nt < 4; nt++)
                    MMA_F16(acc[mt][nt][0], acc[mt][nt][1], acc[mt][nt][2], acc[mt][nt][3],
                            af[mt][0], af[mt][1], af[mt][2], af[mt][3],
                            bf[nt][0], bf[nt][1]);
        }
    }

    // epilogue: pair (q0,q1)/(q2,q3) -> column-adjacent vector stores
    #pragma unroll
    for (int mt = 0; mt < 4; mt++) {
        #pragma unroll
        for (int nt = 0; nt < 4; nt++) {
            #pragma unroll
            for (int half = 0; half < 2; half++) {
                int gm = m0 + wr*64 + mt*16 + (lane >> 2) + half*8;
                int gn = n0 + wc*32 + nt*8 + 2*(lane & 3);
                float v0 = acc[mt][nt][half*2 + 0];
                float v1 = acc[mt][nt][half*2 + 1];
                if (EPI == EPI_PART) {
                    if (gn < N) {
                        float* dst = (float*)Cv + (size_t)blockIdx.z*TOK*PC + (size_t)gm*ldc + gn;
                        dst[0] = v0;
                        if (gn + 1 < N) dst[1] = v1;
                    }
                    continue;
                }
                v0 += bias[gn]; v1 += bias[gn+1];
                if (EPI == EPI_SPLIT_SILU) {
                    float s0 = v0 / (1.f + __expf(-v0));
                    float s1 = v1 / (1.f + __expf(-v1));
                    __half2 hv = __floats2half2_rn(s0, s1);
                    if (gn < Eq) *(__half2*)((__half*)Cv + (size_t)gm*Eq + gn) = hv;
                    else         *(__half2*)(gate + (size_t)gm*Eq + gn - Eq)  = hv;
                } else if (EPI == EPI_SOFTPLUS) {
                    float s0 = (v0 > 20.f) ? v0 : log1pf(__expf(v0));
                    float s1 = (v1 > 20.f) ? v1 : log1pf(__expf(v1));
                    *(__half2*)((__half*)Cv + (size_t)gm*ldc + gn) = __floats2half2_rn(s0, s1);
                } else { // EPI_RES
                    const float2 r2 = *(const float2*)(resid + (size_t)gm*ldc + gn);
                    float2 f2; f2.x = v0 + r2.x; f2.y = v1 + r2.y;
                    *(float2*)((float*)Cv + (size_t)gm*ldc + gn) = f2;
                }
            }
        }
    }
}

// ---------------- chunked selective scan (f16x2 exp + smem B/C) -------------
#define LOG2E 1.4426950408889634f

__global__ void __launch_bounds__(256)
scan_p1(const float* __restrict__ A_log) {
    __shared__ float4 sP[CT][8];
    int gw    = blockIdx.x*8 + (threadIdx.x >> 5);
    int lane  = threadIdx.x & 31;
    int egrp  = gw & 127;
    int chunk = gw >> 7;
    int c = egrp*32 + lane;
    int b = c >> 11;
    int e = c & (Eq-1);
    int t0 = chunk * CT;

    // stage B/C slice (shared by all warps in block: same (b, chunk))
    {
        int gw0 = blockIdx.x*8;
        int b0 = ((gw0 & 127)*32) >> 11;
        int tb0 = (gw0 >> 7) * CT;
        for (int id = threadIdx.x; id < CT*8; id += 256) {
            int t = id >> 3, j = id & 7;
            sP[t][j] = *(const float4*)(g_P + ((size_t)b0*Lq + tb0 + t)*PC + 64 + j*4);
        }
    }
    __syncthreads();

    __half2 Aen2[8];
    #pragma unroll
    for (int p = 0; p < 8; p++) {
        float a0 = -__expf(A_log[e*Nq + 2*p    ]) * LOG2E;
        float a1 = -__expf(A_log[e*Nq + 2*p + 1]) * LOG2E;
        Aen2[p] = __floats2half2_rn(a0, a1);
    }

    float h[Nq], ap[Nq];
    #pragma unroll
    for (int n = 0; n < Nq; n++) { h[n] = 0.f; ap[n] = 1.f; }

    const __half* dp = g_delta + ((size_t)b*Lq + t0)*Eq + e;
    const __half* up = g_u     + ((size_t)b*Lq + t0)*Eq + e;

    #pragma unroll 2
    for (int t = 0; t < CT; t++) {
        __half dh = dp[(size_t)t*Eq];
        float d  = __half2float(dh);
        float xv = __half2float(up[(size_t)t*Eq]);
        float dx = d * xv;
        __half2 dh2 = __half2half2(dh);
        float da[Nq];
        #pragma unroll
        for (int p = 0; p < 8; p++) {
            float2 f = __half22float2(h2exp2(__hmul2(dh2, Aen2[p])));
            da[2*p] = f.x; da[2*p+1] = f.y;
        }
        #pragma unroll
        for (int q = 0; q < 4; q++) {
            float4 Bv = sP[t][q];
            float bb[4] = {Bv.x, Bv.y, Bv.z, Bv.w};
            #pragma unroll
            for (int r = 0; r < 4; r++) {
                int n = q*4 + r;
                ap[n] *= da[n];
                h[n] = fmaf(da[n], h[n], dx * bb[r]);
            }
        }
    }
    float4* apo = (float4*)(g_ap + ((size_t)chunk*NCHAN + c)*Nq);
    float4* co  = (float4*)(g_c  + ((size_t)chunk*NCHAN + c)*Nq);
    #pragma unroll
    for (int q = 0; q < 4; q++) {
        apo[q] = make_float4(ap[q*4], ap[q*4+1], ap[q*4+2], ap[q*4+3]);
        co[q]  = make_float4(h[q*4],  h[q*4+1],  h[q*4+2],  h[q*4+3]);
    }
}

__global__ void __launch_bounds__(256)
scan_p2() {
    int i = blockIdx.x*blockDim.x + threadIdx.x;
    if (i >= NCHAN*Nq) return;
    float hin = 0.f;
    #pragma unroll
    for (int k = 0; k < NCHUNK; k++) {
        size_t idx = (size_t)k*NCHAN*Nq + i;
        g_hin[idx] = hin;
        hin = g_ap[idx]*hin + g_c[idx];
    }
}

__global__ void __launch_bounds__(256)
scan_p3(const float* __restrict__ A_log, const float* __restrict__ Dv) {
    __shared__ float4 sP[CT][8];
    int gw    = blockIdx.x*8 + (threadIdx.x >> 5);
    int lane  = threadIdx.x & 31;
    int egrp  = gw & 127;
    int chunk = gw >> 7;
    int c = egrp*32 + lane;
    int b = c >> 11;
    int e = c & (Eq-1);
    int t0 = chunk * CT;

    {
        int gw0 = blockIdx.x*8;
        int b0 = ((gw0 & 127)*32) >> 11;
        int tb0 = (gw0 >> 7) * CT;
        for (int id = threadIdx.x; id < CT*8; id += 256) {
            int t = id >> 3, j = id & 7;
            sP[t][j] = *(const float4*)(g_P + ((size_t)b0*Lq + tb0 + t)*PC + 64 + j*4);
        }
    }
    __syncthreads();

    __half2 Aen2[8];
    #pragma unroll
    for (int p = 0; p < 8; p++) {
        float a0 = -__expf(A_log[e*Nq + 2*p    ]) * LOG2E;
        float a1 = -__expf(A_log[e*Nq + 2*p + 1]) * LOG2E;
        Aen2[p] = __floats2half2_rn(a0, a1);
    }
    float De = Dv[e];

    float h[Nq];
    const float4* hi = (const float4*)(g_hin + ((size_t)chunk*NCHAN + c)*Nq);
    #pragma unroll
    for (int q = 0; q < 4; q++) {
        float4 v = hi[q];
        h[q*4] = v.x; h[q*4+1] = v.y; h[q*4+2] = v.z; h[q*4+3] = v.w;
    }

    const __half* dp = g_delta + ((size_t)b*Lq + t0)*Eq + e;
    const __half* up = g_u     + ((size_t)b*Lq + t0)*Eq + e;
    const __half* gp = g_gate  + ((size_t)b*Lq + t0)*Eq + e;
    __half*       yp = g_y     + ((size_t)b*Lq + t0)*Eq + e;

    #pragma unroll 2
    for (int t = 0; t < CT; t++) {
        __half dh = dp[(size_t)t*Eq];
        float d  = __half2float(dh);
        float xv = __half2float(up[(size_t)t*Eq]);
        float dx = d * xv;
        __half2 dh2 = __half2half2(dh);
        float da[Nq];
        #pragma unroll
        for (int p = 0; p < 8; p++) {
            float2 f = __half22float2(h2exp2(__hmul2(dh2, Aen2[p])));
            da[2*p] = f.x; da[2*p+1] = f.y;
        }
        float y = 0.f;
        #pragma unroll
        for (int q = 0; q < 4; q++) {
            float4 Bv = sP[t][q];
            float4 Cvv = sP[t][4+q];
            float bb[4] = {Bv.x, Bv.y, Bv.z, Bv.w};
            float cc[4] = {Cvv.x, Cvv.y, Cvv.z, Cvv.w};
            #pragma unroll
            for (int r = 0; r < 4; r++) {
                int n = q*4 + r;
                h[n] = fmaf(da[n], h[n], dx * bb[r]);
                y = fmaf(cc[r], h[n], y);
            }
        }
        float g = __half2float(gp[(size_t)t*Eq]);
        yp[(size_t)t*Eq] = __float2half_rn(fmaf(xv, De, y) * g);
    }
}

// ---------------- launch ----------------
extern "C" void kernel_launch(void* const* d_in, const int* in_sizes, int n_in,
                              void* d_out, int out_size) {
    const float* x       = (const float*)d_in[0];
    const float* lng     = (const float*)d_in[1];
    const float* lnb     = (const float*)d_in[2];
    const float* W_in    = (const float*)d_in[3];
    const float* b_in    = (const float*)d_in[4];
    const float* W_delta = (const float*)d_in[5];
    const float* b_delta = (const float*)d_in[6];
    const float* W_dt    = (const float*)d_in[7];
    const float* b_dt    = (const float*)d_in[8];
    const float* W_B     = (const float*)d_in[9];
    const float* b_B     = (const float*)d_in[10];
    const float* W_C     = (const float*)d_in[11];
    const float* b_C     = (const float*)d_in[12];
    const float* A_log   = (const float*)d_in[13];
    const float* Dv      = (const float*)d_in[14];
    const float* W_out   = (const float*)d_in[15];
    const float* b_out   = (const float*)d_in[16];
    float* out = (float*)d_out;

    void *p_xn, *p_u, *p_gate, *p_Ph, *p_Ppart, *p_delta, *p_y;
    void *p_WcatT, *p_WtIn, *p_WtDt, *p_WtOut;
    cudaGetSymbolAddress(&p_xn,    g_xn);
    cudaGetSymbolAddress(&p_u,     g_u);
    cudaGetSymbolAddress(&p_gate,  g_gate);
    cudaGetSymbolAddress(&p_Ph,    g_Ph);
    cudaGetSymbolAddress(&p_Ppart, g_Ppart);
    cudaGetSymbolAddress(&p_delta, g_delta);
    cudaGetSymbolAddress(&p_y,     g_y);
    cudaGetSymbolAddress(&p_WcatT, g_WcatT);
    cudaGetSymbolAddress(&p_WtIn,  g_WtIn);
    cudaGetSymbolAddress(&p_WtDt,  g_WtDt);
    cudaGetSymbolAddress(&p_WtOut, g_WtOut);

    static bool init_done = false;
    static cudaStream_t s2;
    static cudaEvent_t evFork, evJoin;
    if (!init_done) {
        cudaFuncSetAttribute(gemm_h<EPI_SPLIT_SILU>, cudaFuncAttributeMaxDynamicSharedMemorySize, H_SMEM);
        cudaFuncSetAttribute(gemm_h<EPI_SOFTPLUS>,   cudaFuncAttributeMaxDynamicSharedMemorySize, H_SMEM);
        cudaFuncSetAttribute(gemm_h<EPI_RES>,        cudaFuncAttributeMaxDynamicSharedMemorySize, H_SMEM);
        cudaFuncSetAttribute(gemm_h<EPI_PART>,       cudaFuncAttributeMaxDynamicSharedMemorySize, H_SMEM);
        cudaStreamCreateWithFlags(&s2, cudaStreamNonBlocking);
        cudaEventCreateWithFlags(&evFork, cudaEventDisableTiming);
        cudaEventCreateWithFlags(&evJoin, cudaEventDisableTiming);
        init_done = true;
    }

    // fork: prep (weights) on side stream, LN on main stream, join before GEMM1
    cudaEventRecord(evFork, 0);
    cudaStreamWaitEvent(s2, evFork, 0);
    prep_kernel<<<PREP_BLOCKS, 256, 0, s2>>>(W_in, W_out, W_dt,
                                             W_delta, W_B, W_C, b_delta, b_B, b_C);
    cudaEventRecord(evJoin, s2);
    ln_kernel<<<TOK, 256>>>(x, lng, lnb);
    cudaStreamWaitEvent(0, evJoin, 0);

    // GEMM1: xn @ W_in -> silu(u), silu(gate)
    gemm_h<EPI_SPLIT_SILU><<<dim3(2*Eq/128, TOK/128), 256, H_SMEM>>>(
        (const __half*)p_xn, Hq, (const __half*)p_WtIn, Hq, b_in,
        p_u, Eq, nullptr, (__half*)p_gate, TOK, 2*Eq, Hq, Hq);
    // P partials = u @ Wcat (split-K), reduce (+fp16 copy of delta part)
    gemm_h<EPI_PART><<<dim3(1, TOK/128, KSPLIT), 256, H_SMEM>>>(
        (const __half*)p_u, Eq, (const __half*)p_WcatT, Eq, nullptr,
        p_Ppart, PC, nullptr, nullptr, TOK, PC, Eq, Eq/KSPLIT);
    reduceP_kernel<<<(TOK*PC + 255)/256, 256>>>();
    // delta = softplus(Ph @ W_dt) -> fp16
    gemm_h<EPI_SOFTPLUS><<<dim3(Eq/128, TOK/128), 256, H_SMEM>>>(
        (const __half*)p_Ph, 64, (const __half*)p_WtDt, Rq, b_dt,
        p_delta, Eq, nullptr, nullptr, TOK, Eq, Rq, Rq);
    // chunked selective scan
    scan_p1<<<(NCHAN/32)*NCHUNK/8, 256>>>(A_log);
    scan_p2<<<(NCHAN*Nq + 255)/256, 256>>>();
    scan_p3<<<(NCHAN/32)*NCHUNK/8, 256>>>(A_log, Dv);
    // out = y @ W_out + b_out + residual
    gemm_h<EPI_RES><<<dim3(Hq/128, TOK/128), 256, H_SMEM>>>(
        (const __half*)p_y, Eq, (const __half*)p_WtOut, Eq, b_out,
        out, Hq, x, nullptr, TOK, Hq, Eq, Eq);
}

// round 16
// speedup vs baseline: 1.4532x; 1.2394x over previous
#include <cuda_runtime.h>
#include <cuda.h>
#include <cuda_fp16.h>
#include <math.h>
#include <stdint.h>

// Problem constants
#define Bq   2
#define Lq   2048
#define Hq   1024
#define Eq   2048
#define Nq   16
#define Rq   64
#define TOK  (Bq*Lq)        // 4096 tokens
#define PC   96             // packed proj cols: 64 (delta) + 16 (B) + 16 (C)
#define PCP  128            // padded N for P-GEMM
#define KSPLIT 8
#define NCHUNK 32           // scan chunks
#define CT    (Lq/NCHUNK)   // 64 timesteps per chunk
#define NCHAN (Bq*Eq)       // 4096 channels

// ---------------- device scratch (allocation-free) ----------------
__device__ __align__(16) __half g_xn[TOK*Hq];      // layernormed input (fp16)
__device__ __align__(16) __half g_u[TOK*Eq];       // silu(u) fp16
__device__ __align__(16) __half g_gate[TOK*Eq];    // silu(gate) fp16
__device__ __align__(16) __half g_y[TOK*Eq];       // scan output fp16
__device__ __align__(16) float  g_P[TOK*PC];       // [delta_proj(64) | B(16) | C(16)] f32
__device__ __align__(16) __half g_Ph[TOK*64];      // delta-proj part, fp16 (GEMM input)
__device__ __align__(16) float  g_Ppart[KSPLIT*TOK*PC];
__device__ __align__(16) __half g_delta[TOK*Eq];   // softplus delta fp16
__device__ __align__(16) __half g_WcatT[PCP*Eq];   // [delta|B|C]^T padded, fp16
__device__ float g_bcat[PC];
__device__ __align__(16) __half g_WtIn[2*Eq*Hq];   // W_in^T  [4096][1024] fp16
__device__ __align__(16) __half g_WtDt[Eq*Rq];     // W_dt^T  [2048][64]   fp16
__device__ __align__(16) __half g_WtOut[Hq*Eq];    // W_out^T [1024][2048] fp16
// chunked-scan state: [chunk][chan][n]
__device__ __align__(16) float g_ap [NCHUNK*NCHAN*Nq];
__device__ __align__(16) float g_c  [NCHUNK*NCHAN*Nq];
__device__ __align__(16) float g_hin[NCHUNK*NCHAN*Nq];

__device__ __forceinline__ uint32_t sptr(const void* p) {
    return (uint32_t)__cvta_generic_to_shared(p);
}
__device__ __forceinline__ void mbar_init(uint32_t a, uint32_t cnt) {
    asm volatile("mbarrier.init.shared.b64 [%0], %1;" :: "r"(a), "r"(cnt) : "memory");
}
__device__ __forceinline__ void mbar_expect(uint32_t a, uint32_t bytes) {
    asm volatile("mbarrier.arrive.expect_tx.shared.b64 _, [%0], %1;"
                 :: "r"(a), "r"(bytes) : "memory");
}
__device__ __forceinline__ void mbar_wait(uint32_t a, uint32_t ph) {
    asm volatile("{\n\t.reg .pred P;\n\tWL%=:\n\t"
        "mbarrier.try_wait.parity.acquire.cta.shared::cta.b64 P, [%0], %1, 0x989680;\n\t"
        "@P bra.uni WD%=;\n\tbra.uni WL%=;\n\tWD%=:\n\t}"
        :: "r"(a), "r"(ph) : "memory");
}
__device__ __forceinline__ void tma_ld2d(uint32_t dst, const CUtensorMap* tm,
                                         int cx, int cy, uint32_t mbar) {
    asm volatile("cp.async.bulk.tensor.2d.shared::cta.global.tile.mbarrier::complete_tx::bytes "
                 "[%0], [%1, {%2, %3}], [%4];"
                 :: "r"(dst), "l"(tm), "r"(cx), "r"(cy), "r"(mbar) : "memory");
}

// ---------------- LayerNorm (writes fp16 xn) ----------------
__global__ void ln_kernel(const float* __restrict__ x,
                          const float* __restrict__ gamma,
                          const float* __restrict__ beta) {
    int m = blockIdx.x;
    const float* row = x + (size_t)m*Hq;
    float s = 0.f, s2 = 0.f;
    for (int i = threadIdx.x; i < Hq; i += blockDim.x) {
        float v = row[i]; s += v; s2 += v*v;
    }
    __shared__ float sh[64];
    for (int o = 16; o; o >>= 1) {
        s  += __shfl_xor_sync(~0u, s,  o);
        s2 += __shfl_xor_sync(~0u, s2, o);
    }
    int wid = threadIdx.x >> 5, lane = threadIdx.x & 31;
    if (lane == 0) { sh[wid] = s; sh[32+wid] = s2; }
    __syncthreads();
    if (wid == 0) {
        int nw = blockDim.x >> 5;
        s  = (lane < nw) ? sh[lane]    : 0.f;
        s2 = (lane < nw) ? sh[32+lane] : 0.f;
        for (int o = 16; o; o >>= 1) {
            s  += __shfl_xor_sync(~0u, s,  o);
            s2 += __shfl_xor_sync(~0u, s2, o);
        }
        if (lane == 0) { sh[0] = s; sh[1] = s2; }
    }
    __syncthreads();
    float mu  = sh[0] * (1.f/Hq);
    float var = sh[1] * (1.f/Hq) - mu*mu;
    float inv = rsqrtf(var + 1e-5f);
    for (int i = threadIdx.x; i < Hq; i += blockDim.x) {
        g_xn[(size_t)m*Hq + i] = __float2half_rn((row[i]-mu)*inv*gamma[i] + beta[i]);
    }
}

// ---------------- fused prep: 3 transposes + pack, one launch ----------------
#define PREP_BLOCKS 7296
__global__ void prep_kernel(const float* __restrict__ W_in,
                            const float* __restrict__ W_out,
                            const float* __restrict__ W_dt,
                            const float* __restrict__ Wd, const float* __restrict__ Wb,
                            const float* __restrict__ Wc, const float* __restrict__ bd,
                            const float* __restrict__ bb, const float* __restrict__ bc) {
    int blk = blockIdx.x;
    if (blk < 6272) {
        const float* src; __half* dst; int R, Cc, bx, nbx;
        if (blk < 4096)      { src = W_in;  dst = g_WtIn;  R = Hq; Cc = 2*Eq; bx = blk;        nbx = 2*Eq/32; }
        else if (blk < 6144) { src = W_out; dst = g_WtOut; R = Eq; Cc = Hq;   bx = blk - 4096; nbx = Hq/32; }
        else                 { src = W_dt;  dst = g_WtDt;  R = Rq; Cc = Eq;   bx = blk - 6144; nbx = Eq/32; }
        int c0 = (bx % nbx) * 32, r0 = (bx / nbx) * 32;
        int tx = threadIdx.x & 31, ty = threadIdx.x >> 5;
        __shared__ float t[32][33];
        for (int i = ty; i < 32; i += 8)
            t[i][tx] = src[(size_t)(r0+i)*Cc + c0 + tx];
        __syncthreads();
        for (int i = ty; i < 32; i += 8)
            dst[(size_t)(c0+i)*R + r0 + tx] = __float2half_rn(t[tx][i]);
    } else {
        int i = (blk - 6272)*256 + threadIdx.x;
        if (i < PCP*Eq) {
            int c = i / Eq, k = i % Eq;
            float v = 0.f;
            if (c < 64)      v = Wd[k*64 + c];
            else if (c < 80) v = Wb[k*16 + (c-64)];
            else if (c < 96) v = Wc[k*16 + (c-80)];
            g_WcatT[i] = __float2half_rn(v);
        }
        if (i < PC) {
            g_bcat[i] = (i < 64) ? bd[i] : ((i < 80) ? bb[i-64] : bc[i-80]);
        }
    }
}

// ---------------- split-K reduction for P (f32 + fp16 delta part) -----------
__global__ void reduceP_kernel() {
    int i = blockIdx.x*blockDim.x + threadIdx.x;
    if (i >= TOK*PC) return;
    int c = i % PC, m = i / PC;
    float s = g_bcat[c];
    #pragma unroll
    for (int z = 0; z < KSPLIT; z++) s += g_Ppart[(size_t)z*TOK*PC + i];
    g_P[i] = s;
    if (c < 64) g_Ph[(size_t)m*64 + c] = __float2half_rn(s);
}

// ======== fp16 m16n8k16 GEMM, 8 warps, BK=64, 3-stage TMA 2D ================
enum { EPI_SPLIT_SILU = 1, EPI_SOFTPLUS = 2, EPI_RES = 3, EPI_PART = 4 };

#define MMA_F16(c0,c1,c2,c3,a0,a1,a2,a3,b0,b1) \
    asm volatile("mma.sync.aligned.m16n8k16.row.col.f32.f16.f16.f32 " \
                 "{%0,%1,%2,%3},{%4,%5,%6,%7},{%8,%9},{%0,%1,%2,%3};" \
                 : "+f"(c0),"+f"(c1),"+f"(c2),"+f"(c3) \
                 : "r"(a0),"r"(a1),"r"(a2),"r"(a3),"r"(b0),"r"(b1))

#define LDSM_X4(r0,r1,r2,r3,addr) \
    asm volatile("ldmatrix.sync.aligned.m8n8.x4.shared.b16 {%0,%1,%2,%3}, [%4];" \
                 : "=r"(r0),"=r"(r1),"=r"(r2),"=r"(r3) : "r"(addr))

#define HBM 128
#define HBN 128
#define HBK 64
#define HSTAGE 3
#define HSTG_B 16384                 // bytes per stage tile (128 rows x 128B, SW128)
#define H_TILES (HSTAGE*HSTG_B*2)    // A+B bytes (98304)
#define H_SMEM (H_TILES + 32)        // + mbarriers

template<int EPI>
__global__ void __launch_bounds__(256, 2)
gemm_t(const __grid_constant__ CUtensorMap tmA,
       const __grid_constant__ CUtensorMap tmB,
       const float* __restrict__ bias,
       void* __restrict__ Cv, int ldc,
       const float* __restrict__ resid,           // residual (RES)
       __half* __restrict__ gate,                 // gate out (SPLIT_SILU)
       int M, int N, int K, int Kchunk)
{
    extern __shared__ __align__(1024) __half smh[];
    const uint32_t aBase = sptr(smh);
    const uint32_t bBase = aBase + HSTAGE*HSTG_B;
    const uint32_t mbar  = aBase + H_TILES;

    const int tid  = threadIdx.x;
    const int lane = tid & 31;
    const int warp = tid >> 5;
    const int wr   = warp & 1;          // 2 x 64 rows
    const int wc   = warp >> 1;         // 4 x 32 cols
    const int m0   = blockIdx.y * HBM;
    const int n0   = blockIdx.x * HBN;
    const int Koff = blockIdx.z * Kchunk;

    const uint32_t aRow = wr*64 + (lane & 15);
    const uint32_t aSlot = lane >> 4;            // +0/+1 16B slot
    const uint32_t bRow = wc*32 + (lane & 7) + ((lane >> 4) << 3);
    const uint32_t bSlot = (lane >> 3) & 1;

    if (tid < HSTAGE) mbar_init(mbar + tid*8, 1);
    __syncthreads();

    auto issue = [&](int it, int buf) {
        if (tid == 0) {
            int k0 = Koff + it * HBK;
            uint32_t mb = mbar + buf*8;
            mbar_expect(mb, 2*HSTG_B);
            tma_ld2d(aBase + buf*HSTG_B, &tmA, k0, m0, mb);
            tma_ld2d(bBase + buf*HSTG_B, &tmB, k0, n0, mb);
        }
    };

    float acc[4][4][4];
    #pragma unroll
    for (int i = 0; i < 4; i++)
        #pragma unroll
        for (int j = 0; j < 4; j++)
            #pragma unroll
            for (int k = 0; k < 4; k++) acc[i][j][k] = 0.f;

    const int nIter = Kchunk / HBK;
    #pragma unroll
    for (int s = 0; s < HSTAGE-1; s++)
        if (s < nIter) issue(s, s);

    for (int it = 0; it < nIter; it++) {
        int buf = it % HSTAGE;
        mbar_wait(mbar + buf*8, (it / HSTAGE) & 1);
        __syncthreads();
        int nx = it + HSTAGE - 1;
        if (nx < nIter) issue(nx, nx % HSTAGE);

        uint32_t aB = aBase + buf*HSTG_B;
        uint32_t bB = bBase + buf*HSTG_B;

        #pragma unroll
        for (int kk = 0; kk < 4; kk++) {
            uint32_t af[4][4], bf[4][2];
            #pragma unroll
            for (int mt = 0; mt < 4; mt++) {
                uint32_t r = aRow + mt*16;
                uint32_t phys = (kk*2 + aSlot) ^ (r & 7);
                LDSM_X4(af[mt][0], af[mt][1], af[mt][2], af[mt][3],
                        aB + r*128 + phys*16);
            }
            #pragma unroll
            for (int ntp = 0; ntp < 2; ntp++) {
                uint32_t r = bRow + ntp*16;
                uint32_t phys = (kk*2 + bSlot) ^ (r & 7);
                LDSM_X4(bf[2*ntp][0], bf[2*ntp][1], bf[2*ntp+1][0], bf[2*ntp+1][1],
                        bB + r*128 + phys*16);
            }
            #pragma unroll
            for (int mt = 0; mt < 4; mt++)
                #pragma unroll
                for (int nt = 0; nt < 4; nt++)
                    MMA_F16(acc[mt][nt][0], acc[mt][nt][1], acc[mt][nt][2], acc[mt][nt][3],
                            af[mt][0], af[mt][1], af[mt][2], af[mt][3],
                            bf[nt][0], bf[nt][1]);
        }
    }

    // epilogue: pair (q0,q1)/(q2,q3) -> column-adjacent vector stores
    #pragma unroll
    for (int mt = 0; mt < 4; mt++) {
        #pragma unroll
        for (int nt = 0; nt < 4; nt++) {
            #pragma unroll
            for (int half = 0; half < 2; half++) {
                int gm = m0 + wr*64 + mt*16 + (lane >> 2) + half*8;
                int gn = n0 + wc*32 + nt*8 + 2*(lane & 3);
                float v0 = acc[mt][nt][half*2 + 0];
                float v1 = acc[mt][nt][half*2 + 1];
                if (EPI == EPI_PART) {
                    if (gn < N) {
                        float* dst = (float*)Cv + (size_t)blockIdx.z*TOK*PC + (size_t)gm*ldc + gn;
                        dst[0] = v0;
                        if (gn + 1 < N) dst[1] = v1;
                    }
                    continue;
                }
                v0 += bias[gn]; v1 += bias[gn+1];
                if (EPI == EPI_SPLIT_SILU) {
                    float s0 = v0 / (1.f + __expf(-v0));
                    float s1 = v1 / (1.f + __expf(-v1));
                    __half2 hv = __floats2half2_rn(s0, s1);
                    if (gn < Eq) *(__half2*)((__half*)Cv + (size_t)gm*Eq + gn) = hv;
                    else         *(__half2*)(gate + (size_t)gm*Eq + gn - Eq)  = hv;
                } else if (EPI == EPI_SOFTPLUS) {
                    float s0 = (v0 > 20.f) ? v0 : log1pf(__expf(v0));
                    float s1 = (v1 > 20.f) ? v1 : log1pf(__expf(v1));
                    *(__half2*)((__half*)Cv + (size_t)gm*ldc + gn) = __floats2half2_rn(s0, s1);
                } else { // EPI_RES
                    const float2 r2 = *(const float2*)(resid + (size_t)gm*ldc + gn);
                    float2 f2; f2.x = v0 + r2.x; f2.y = v1 + r2.y;
                    *(float2*)((float*)Cv + (size_t)gm*ldc + gn) = f2;
                }
            }
        }
    }
}

// ---------------- chunked selective scan (f16x2 exp + smem B/C) -------------
#define LOG2E 1.4426950408889634f

__global__ void __launch_bounds__(256)
scan_p1(const float* __restrict__ A_log) {
    __shared__ float4 sP[CT][8];
    int gw    = blockIdx.x*8 + (threadIdx.x >> 5);
    int lane  = threadIdx.x & 31;
    int egrp  = gw & 127;
    int chunk = gw >> 7;
    int c = egrp*32 + lane;
    int b = c >> 11;
    int e = c & (Eq-1);
    int t0 = chunk * CT;

    {
        int gw0 = blockIdx.x*8;
        int b0 = ((gw0 & 127)*32) >> 11;
        int tb0 = (gw0 >> 7) * CT;
        for (int id = threadIdx.x; id < CT*8; id += 256) {
            int t = id >> 3, j = id & 7;
            sP[t][j] = *(const float4*)(g_P + ((size_t)b0*Lq + tb0 + t)*PC + 64 + j*4);
        }
    }
    __syncthreads();

    __half2 Aen2[8];
    #pragma unroll
    for (int p = 0; p < 8; p++) {
        float a0 = -__expf(A_log[e*Nq + 2*p    ]) * LOG2E;
        float a1 = -__expf(A_log[e*Nq + 2*p + 1]) * LOG2E;
        Aen2[p] = __floats2half2_rn(a0, a1);
    }

    float h[Nq], ap[Nq];
    #pragma unroll
    for (int n = 0; n < Nq; n++) { h[n] = 0.f; ap[n] = 1.f; }

    const __half* dp = g_delta + ((size_t)b*Lq + t0)*Eq + e;
    const __half* up = g_u     + ((size_t)b*Lq + t0)*Eq + e;

    #pragma unroll 2
    for (int t = 0; t < CT; t++) {
        __half dh = dp[(size_t)t*Eq];
        float d  = __half2float(dh);
        float xv = __half2float(up[(size_t)t*Eq]);
        float dx = d * xv;
        __half2 dh2 = __half2half2(dh);
        float da[Nq];
        #pragma unroll
        for (int p = 0; p < 8; p++) {
            float2 f = __half22float2(h2exp2(__hmul2(dh2, Aen2[p])));
            da[2*p] = f.x; da[2*p+1] = f.y;
        }
        #pragma unroll
        for (int q = 0; q < 4; q++) {
            float4 Bv = sP[t][q];
            float bb[4] = {Bv.x, Bv.y, Bv.z, Bv.w};
            #pragma unroll
            for (int r = 0; r < 4; r++) {
                int n = q*4 + r;
                ap[n] *= da[n];
                h[n] = fmaf(da[n], h[n], dx * bb[r]);
            }
        }
    }
    float4* apo = (float4*)(g_ap + ((size_t)chunk*NCHAN + c)*Nq);
    float4* co  = (float4*)(g_c  + ((size_t)chunk*NCHAN + c)*Nq);
    #pragma unroll
    for (int q = 0; q < 4; q++) {
        apo[q] = make_float4(ap[q*4], ap[q*4+1], ap[q*4+2], ap[q*4+3]);
        co[q]  = make_float4(h[q*4],  h[q*4+1],  h[q*4+2],  h[q*4+3]);
    }
}

__global__ void __launch_bounds__(256)
scan_p2() {
    int i = blockIdx.x*blockDim.x + threadIdx.x;
    if (i >= NCHAN*Nq) return;
    float hin = 0.f;
    #pragma unroll
    for (int k = 0; k < NCHUNK; k++) {
        size_t idx = (size_t)k*NCHAN*Nq + i;
        g_hin[idx] = hin;
        hin = g_ap[idx]*hin + g_c[idx];
    }
}

__global__ void __launch_bounds__(256)
scan_p3(const float* __restrict__ A_log, const float* __restrict__ Dv) {
    __shared__ float4 sP[CT][8];
    int gw    = blockIdx.x*8 + (threadIdx.x >> 5);
    int lane  = threadIdx.x & 31;
    int egrp  = gw & 127;
    int chunk = gw >> 7;
    int c = egrp*32 + lane;
    int b = c >> 11;
    int e = c & (Eq-1);
    int t0 = chunk * CT;

    {
        int gw0 = blockIdx.x*8;
        int b0 = ((gw0 & 127)*32) >> 11;
        int tb0 = (gw0 >> 7) * CT;
        for (int id = threadIdx.x; id < CT*8; id += 256) {
            int t = id >> 3, j = id & 7;
            sP[t][j] = *(const float4*)(g_P + ((size_t)b0*Lq + tb0 + t)*PC + 64 + j*4);
        }
    }
    __syncthreads();

    __half2 Aen2[8];
    #pragma unroll
    for (int p = 0; p < 8; p++) {
        float a0 = -__expf(A_log[e*Nq + 2*p    ]) * LOG2E;
        float a1 = -__expf(A_log[e*Nq + 2*p + 1]) * LOG2E;
        Aen2[p] = __floats2half2_rn(a0, a1);
    }
    float De = Dv[e];

    float h[Nq];
    const float4* hi = (const float4*)(g_hin + ((size_t)chunk*NCHAN + c)*Nq);
    #pragma unroll
    for (int q = 0; q < 4; q++) {
        float4 v = hi[q];
        h[q*4] = v.x; h[q*4+1] = v.y; h[q*4+2] = v.z; h[q*4+3] = v.w;
    }

    const __half* dp = g_delta + ((size_t)b*Lq + t0)*Eq + e;
    const __half* up = g_u     + ((size_t)b*Lq + t0)*Eq + e;
    const __half* gp = g_gate  + ((size_t)b*Lq + t0)*Eq + e;
    __half*       yp = g_y     + ((size_t)b*Lq + t0)*Eq + e;

    #pragma unroll 2
    for (int t = 0; t < CT; t++) {
        __half dh = dp[(size_t)t*Eq];
        float d  = __half2float(dh);
        float xv = __half2float(up[(size_t)t*Eq]);
        float dx = d * xv;
        __half2 dh2 = __half2half2(dh);
        float da[Nq];
        #pragma unroll
        for (int p = 0; p < 8; p++) {
            float2 f = __half22float2(h2exp2(__hmul2(dh2, Aen2[p])));
            da[2*p] = f.x; da[2*p+1] = f.y;
        }
        float y = 0.f;
        #pragma unroll
        for (int q = 0; q < 4; q++) {
            float4 Bv = sP[t][q];
            float4 Cvv = sP[t][4+q];
            float bb[4] = {Bv.x, Bv.y, Bv.z, Bv.w};
            float cc[4] = {Cvv.x, Cvv.y, Cvv.z, Cvv.w};
            #pragma unroll
            for (int r = 0; r < 4; r++) {
                int n = q*4 + r;
                h[n] = fmaf(da[n], h[n], dx * bb[r]);
                y = fmaf(cc[r], h[n], y);
            }
        }
        float g = __half2float(gp[(size_t)t*Eq]);
        yp[(size_t)t*Eq] = __float2half_rn(fmaf(xv, De, y) * g);
    }
}

// ---------------- host: tensor-map helper ----------------
typedef CUresult (*EncodeFn)(CUtensorMap*, CUtensorMapDataType, cuuint32_t, void*,
                             const cuuint64_t*, const cuuint64_t*, const cuuint32_t*,
                             const cuuint32_t*, CUtensorMapInterleave, CUtensorMapSwizzle,
                             CUtensorMapL2promotion, CUtensorMapFloatOOBfill);
static EncodeFn s_encode = nullptr;

static void make_map(CUtensorMap* m, void* base, uint64_t d0, uint64_t d1) {
    cuuint64_t dims[2]    = {d0, d1};
    cuuint64_t strides[1] = {d0 * 2};
    cuuint32_t box[2]     = {64, 128};
    cuuint32_t es[2]      = {1, 1};
    s_encode(m, CU_TENSOR_MAP_DATA_TYPE_UINT16, 2, base, dims, strides, box, es,
             CU_TENSOR_MAP_INTERLEAVE_NONE, CU_TENSOR_MAP_SWIZZLE_128B,
             CU_TENSOR_MAP_L2_PROMOTION_L2_128B, CU_TENSOR_MAP_FLOAT_OOB_FILL_NONE);
}

// ---------------- launch ----------------
extern "C" void kernel_launch(void* const* d_in, const int* in_sizes, int n_in,
                              void* d_out, int out_size) {
    const float* x       = (const float*)d_in[0];
    const float* lng     = (const float*)d_in[1];
    const float* lnb     = (const float*)d_in[2];
    const float* W_in    = (const float*)d_in[3];
    const float* b_in    = (const float*)d_in[4];
    const float* W_delta = (const float*)d_in[5];
    const float* b_delta = (const float*)d_in[6];
    const float* W_dt    = (const float*)d_in[7];
    const float* b_dt    = (const float*)d_in[8];
    const float* W_B     = (const float*)d_in[9];
    const float* b_B     = (const float*)d_in[10];
    const float* W_C     = (const float*)d_in[11];
    const float* b_C     = (const float*)d_in[12];
    const float* A_log   = (const float*)d_in[13];
    const float* Dv      = (const float*)d_in[14];
    const float* W_out   = (const float*)d_in[15];
    const float* b_out   = (const float*)d_in[16];
    float* out = (float*)d_out;

    void *p_xn, *p_u, *p_gate, *p_Ph, *p_Ppart, *p_delta, *p_y;
    void *p_WcatT, *p_WtIn, *p_WtDt, *p_WtOut;
    cudaGetSymbolAddress(&p_xn,    g_xn);
    cudaGetSymbolAddress(&p_u,     g_u);
    cudaGetSymbolAddress(&p_gate,  g_gate);
    cudaGetSymbolAddress(&p_Ph,    g_Ph);
    cudaGetSymbolAddress(&p_Ppart, g_Ppart);
    cudaGetSymbolAddress(&p_delta, g_delta);
    cudaGetSymbolAddress(&p_y,     g_y);
    cudaGetSymbolAddress(&p_WcatT, g_WcatT);
    cudaGetSymbolAddress(&p_WtIn,  g_WtIn);
    cudaGetSymbolAddress(&p_WtDt,  g_WtDt);
    cudaGetSymbolAddress(&p_WtOut, g_WtOut);

    static bool init_done = false;
    static cudaStream_t s2;
    static cudaEvent_t evFork, evJoin;
    if (!init_done) {
        cudaFuncSetAttribute(gemm_t<EPI_SPLIT_SILU>, cudaFuncAttributeMaxDynamicSharedMemorySize, H_SMEM);
        cudaFuncSetAttribute(gemm_t<EPI_SOFTPLUS>,   cudaFuncAttributeMaxDynamicSharedMemorySize, H_SMEM);
        cudaFuncSetAttribute(gemm_t<EPI_RES>,        cudaFuncAttributeMaxDynamicSharedMemorySize, H_SMEM);
        cudaFuncSetAttribute(gemm_t<EPI_PART>,       cudaFuncAttributeMaxDynamicSharedMemorySize, H_SMEM);
        cudaStreamCreateWithFlags(&s2, cudaStreamNonBlocking);
        cudaEventCreateWithFlags(&evFork, cudaEventDisableTiming);
        cudaEventCreateWithFlags(&evJoin, cudaEventDisableTiming);
        cudaDriverEntryPointQueryResult qr;
        void* fp = nullptr;
        cudaGetDriverEntryPoint("cuTensorMapEncodeTiled", &fp, cudaEnableDefault, &qr);
        s_encode = (EncodeFn)fp;
        init_done = true;
    }

    // tensor maps (host-side, per call; capture-legal)
    CUtensorMap mA1, mB1, mAP, mBP, mAD, mBD, mAO, mBO;
    make_map(&mA1, p_xn,    Hq, TOK);      // GEMM1 A: xn [4096 x 1024]
    make_map(&mB1, p_WtIn,  Hq, 2*Eq);     // GEMM1 B: W_in^T [4096 x 1024]
    make_map(&mAP, p_u,     Eq, TOK);      // P A: u [4096 x 2048]
    make_map(&mBP, p_WcatT, Eq, PCP);      // P B: Wcat^T [128 x 2048]
    make_map(&mAD, p_Ph,    64, TOK);      // delta A: Ph [4096 x 64]
    make_map(&mBD, p_WtDt,  64, Eq);       // delta B: W_dt^T [2048 x 64]
    make_map(&mAO, p_y,     Eq, TOK);      // out A: y [4096 x 2048]
    make_map(&mBO, p_WtOut, Eq, Hq);       // out B: W_out^T [1024 x 2048]

    // fork: prep (weights) on side stream, LN on main stream, join before GEMM1
    cudaEventRecord(evFork, 0);
    cudaStreamWaitEvent(s2, evFork, 0);
    prep_kernel<<<PREP_BLOCKS, 256, 0, s2>>>(W_in, W_out, W_dt,
                                             W_delta, W_B, W_C, b_delta, b_B, b_C);
    cudaEventRecord(evJoin, s2);
    ln_kernel<<<TOK, 256>>>(x, lng, lnb);
    cudaStreamWaitEvent(0, evJoin, 0);

    // GEMM1: xn @ W_in -> silu(u), silu(gate)
    gemm_t<EPI_SPLIT_SILU><<<dim3(2*Eq/128, TOK/128), 256, H_SMEM>>>(
        mA1, mB1, b_in, p_u, Eq, nullptr, (__half*)p_gate, TOK, 2*Eq, Hq, Hq);
    // P partials = u @ Wcat (split-K), reduce (+fp16 copy of delta part)
    gemm_t<EPI_PART><<<dim3(1, TOK/128, KSPLIT), 256, H_SMEM>>>(
        mAP, mBP, nullptr, p_Ppart, PC, nullptr, nullptr, TOK, PC, Eq, Eq/KSPLIT);
    reduceP_kernel<<<(TOK*PC + 255)/256, 256>>>();
    // delta = softplus(Ph @ W_dt) -> fp16
    gemm_t<EPI_SOFTPLUS><<<dim3(Eq/128, TOK/128), 256, H_SMEM>>>(
        mAD, mBD, b_dt, p_delta, Eq, nullptr, nullptr, TOK, Eq, Rq, Rq);
    // chunked selective scan
    scan_p1<<<(NCHAN/32)*NCHUNK/8, 256>>>(A_log);
    scan_p2<<<(NCHAN*Nq + 255)/256, 256>>>();
    scan_p3<<<(NCHAN/32)*NCHUNK/8, 256>>>(A_log, Dv);
    // out = y @ W_out + b_out + residual
    gemm_t<EPI_RES><<<dim3(Hq/128, TOK/128), 256, H_SMEM>>>(
        mAO, mBO, b_out, out, Hq, x, nullptr, TOK, Hq, Eq, Eq);
}